// round 11
// baseline (speedup 1.0000x reference)
#include <cuda_runtime.h>
#include <cuda_bf16.h>
#include <cstdint>

#define B4    4
#define NPTS  256
#define KNN   27
#define MAXC  3072
#define VTOT  4080
// bf16 A-pool offsets (elements)
#define AV2   0L
#define ASH2  294912L
#define AV3   589824L
#define ASH3  5308416L
#define W4V   10027008L
#define W4S   11075584L
#define ABFN  12124160L
// bf16 B-pool offsets
#define XV    0L
#define XSH   4194304L
#define BBFN  5242880L

__device__ __align__(256) float g_A    [B4 * NPTS * MAXC];
__device__ __align__(256) float g_B2   [B4 * NPTS * MAXC];
__device__ __align__(256) float g_Ash  [2 * NPTS * MAXC];
__device__ __align__(256) float g_Bsh  [2 * NPTS * MAXC];
__device__ __align__(256) float g_maxh [B4 * NPTS * MAXC];
__device__ __align__(256) float g_minh [B4 * NPTS * MAXC];
__device__ __align__(256) float g_sumh [B4 * NPTS * MAXC];
__device__ __align__(256) float g_sumsq[B4 * NPTS * MAXC];
__device__ __align__(256) float g_Xvar [B4 * 64 * NPTS];     // fp32 L0 out only
__device__ __align__(256) float g_Xsh  [64 * NPTS];
__device__ __align__(256) float g_ypv  [32 * 256 * NPTS];
__device__ __align__(256) float g_yps  [8 * 256 * NPTS];
__device__ __align__(256) float g_st   [2 * MAXC];
__device__ __align__(256) float g_P0   [B4 * 3 * NPTS];
__device__ __align__(256) int   g_idx  [B4 * NPTS * KNN];
__device__ __align__(256) __nv_bfloat16 g_Ahi[ABFN];
__device__ __align__(256) __nv_bfloat16 g_Alo[ABFN];
__device__ __align__(256) __nv_bfloat16 g_Bhi[BBFN];
__device__ __align__(256) __nv_bfloat16 g_Blo[BBFN];

// ---------------------------------------------------------------------------
__global__ void xpose_kernel(const float* __restrict__ x, float* __restrict__ P0)
{
    int id = blockIdx.x * 256 + threadIdx.x;
    if (id >= B4 * 3 * NPTS) return;
    int b = id / (3 * NPTS), r = id % (3 * NPTS);
    P0[id] = x[((long)b * NPTS + (r % NPTS)) * 3 + (r / NPTS)];
}

// ---------------------------------------------------------------------------
__global__ void knn_kernel(const float* __restrict__ x, int* __restrict__ idxout)
{
    __shared__ float px[NPTS], py[NPTS], pz[NPTS];
    int b = blockIdx.y, t = threadIdx.x;
    int w = t >> 5, lane = t & 31;
    {
        const float* xb = x + (long)b * NPTS * 3;
        px[t] = xb[t * 3 + 0]; py[t] = xb[t * 3 + 1]; pz[t] = xb[t * 3 + 2];
    }
    __syncthreads();
    int i = blockIdx.x * 8 + w;
    float xi = px[i], yi = py[i], zi = pz[i];
    float d[8];
#pragma unroll
    for (int m = 0; m < 8; m++) {
        int j = lane + 32 * m;
        float dx = xi - px[j], dy = yi - py[j], dz = zi - pz[j];
        d[m] = __fadd_rn(__fadd_rn(__fmul_rn(dx, dx), __fmul_rn(dy, dy)), __fmul_rn(dz, dz));
    }
    for (int k = 0; k < KNN; k++) {
        float bv = d[0]; int bm = 0;
#pragma unroll
        for (int m = 1; m < 8; m++) if (d[m] < bv) { bv = d[m]; bm = m; }
        int bj = lane + 32 * bm;
#pragma unroll
        for (int off = 16; off > 0; off >>= 1) {
            float ov = __shfl_down_sync(0xffffffffu, bv, off);
            int   oj = __shfl_down_sync(0xffffffffu, bj, off);
            if (ov < bv || (ov == bv && oj < bj)) { bv = ov; bj = oj; }
        }
        bj = __shfl_sync(0xffffffffu, bj, 0);
        if (lane == 0) idxout[((long)b * NPTS + i) * KNN + k] = bj;
        if ((bj & 31) == lane) {
            int m = bj >> 5;
#pragma unroll
            for (int mm = 0; mm < 8; mm++) if (mm == m) d[mm] = 3.4e38f;
        }
    }
}

// ---------------------------------------------------------------------------
// Vectorized, division-free weight split; 2 rows per thread for MLP=2.
// grid: (ceil(Cp/256), Cout/2).
__global__ void wsplit_kernel(const float* __restrict__ w, int Cout, int Cp,
                              __nv_bfloat16* __restrict__ Avh, __nv_bfloat16* __restrict__ Avl,
                              __nv_bfloat16* __restrict__ Ash, __nv_bfloat16* __restrict__ Asl)
{
    int c4 = blockIdx.x * 256 + threadIdx.x;
    if (c4 >= Cp) return;
    int Cp4 = Cp >> 2;
    int q = (c4 >= Cp4) + (c4 >= 2 * Cp4) + (c4 >= 3 * Cp4);
    int k4 = c4 - q * Cp4;
    __nv_bfloat16* ph = ((q & 1) == 0) ? Avh : Ash;
    __nv_bfloat16* pl = ((q & 1) == 0) ? Avl : Asl;
    float4 vv[2];
#pragma unroll
    for (int r = 0; r < 2; r++) {
        int m = blockIdx.y * 2 + r;
        vv[r] = reinterpret_cast<const float4*>(w)[(long)m * Cp + c4];
    }
#pragma unroll
    for (int r = 0; r < 2; r++) {
        int m = blockIdx.y * 2 + r;
        float4 v = vv[r];
        __nv_bfloat16 hx = __float2bfloat16(v.x), hy = __float2bfloat16(v.y);
        __nv_bfloat16 hz = __float2bfloat16(v.z), hw = __float2bfloat16(v.w);
        __nv_bfloat16 lx = __float2bfloat16(v.x - __bfloat162float(hx));
        __nv_bfloat16 ly = __float2bfloat16(v.y - __bfloat162float(hy));
        __nv_bfloat16 lz = __float2bfloat16(v.z - __bfloat162float(hz));
        __nv_bfloat16 lw = __float2bfloat16(v.w - __bfloat162float(hw));
        long dst = (long)((q >= 2) ? m + Cout : m) * Cp + k4 * 4;
        *reinterpret_cast<__nv_bfloat162*>(ph + dst)     = __halves2bfloat162(hx, hy);
        *reinterpret_cast<__nv_bfloat162*>(ph + dst + 2) = __halves2bfloat162(hz, hw);
        *reinterpret_cast<__nv_bfloat162*>(pl + dst)     = __halves2bfloat162(lx, ly);
        *reinterpret_cast<__nv_bfloat162*>(pl + dst + 2) = __halves2bfloat162(lz, lw);
    }
}

// ---------------------------------------------------------------------------
__global__ void w4split_kernel(const float* __restrict__ w4,
                               __nv_bfloat16* __restrict__ Avh, __nv_bfloat16* __restrict__ Avl,
                               __nv_bfloat16* __restrict__ Ash, __nv_bfloat16* __restrict__ Asl)
{
    int id = blockIdx.x * 256 + threadIdx.x;
    if (id >= 256 * 4096) return;
    int o = id >> 12, vc = id & 4095;
    float vv = 0.f, vs = 0.f;
    if (vc < VTOT) {
        int CL, off4, voff;
        if (vc < 48)        { CL = 48;   off4 = 0;    voff = 0;    }
        else if (vc < 240)  { CL = 192;  off4 = 96;   voff = 48;   }
        else if (vc < 1008) { CL = 768;  off4 = 480;  voff = 240;  }
        else                { CL = 3072; off4 = 2016; voff = 1008; }
        int c = vc - voff;
        vv = w4[(long)o * 8160 + off4 + c];
        vs = w4[(long)o * 8160 + off4 + CL + c];
    }
    __nv_bfloat16 h1 = __float2bfloat16(vv);
    Avh[id] = h1; Avl[id] = __float2bfloat16(vv - __bfloat162float(h1));
    __nv_bfloat16 h2 = __float2bfloat16(vs);
    Ash[id] = h2; Asl[id] = __float2bfloat16(vs - __bfloat162float(h2));
}

// ---------------------------------------------------------------------------
// SIMT GEMM for layers 0-1 (proven R2 version)
__global__ __launch_bounds__(256, 2)
void gemm_kernel(const float* __restrict__ P, long pstride,
                 const float* __restrict__ W, int ldw, int coffA, int coffB,
                 int Cout, int Mrows, int Kc,
                 const float* __restrict__ addA, const float* __restrict__ addB,
                 int nAdd, long addstride,
                 float* __restrict__ outA, float* __restrict__ outB,
                 long osplit, long obatch, long on, long oo,
                 int S, int kchunk)
{
    int z  = blockIdx.z;
    int b  = z / S, si = z - b * S;
    int kbeg = si * kchunk;
    int kend = min(Kc, kbeg + kchunk);
    int o0 = blockIdx.x * 128, n0 = blockIdx.y * 64;
    int t  = threadIdx.x;
    int tx = t & 15, ty = t >> 4;

    __shared__ float sP[2][16][68];
    __shared__ float sW[2][16][132];

    float acc[4][8];
#pragma unroll
    for (int i = 0; i < 4; i++)
#pragma unroll
        for (int j = 0; j < 8; j++) acc[i][j] = 0.f;

    const float* Pb = P + (long)b * pstride;
    int pc = t >> 4;
    int pn = n0 + (t & 15) * 4;
    float4 rp;
    float  rw[8];

    auto ldP = [&](int k0) {
        int c = k0 + pc;
        if (c < kend) rp = *(const float4*)(Pb + (long)c * NPTS + pn);
        else          rp = make_float4(0.f, 0.f, 0.f, 0.f);
    };
    auto ldW = [&](int k0) {
#pragma unroll
        for (int i = 0; i < 2; i++) {
            int id = t + 256 * i;
            int o  = o0 + (id >> 2);
            int c4 = (id & 3) * 4;
            bool orow = (o < Mrows);
            const float* wp = W + (orow ?
                ((long)((o < Cout) ? o : (o - Cout)) * ldw + ((o < Cout) ? coffA : coffB)) : 0);
#pragma unroll
            for (int j = 0; j < 4; j++) {
                int c = k0 + c4 + j;
                rw[i * 4 + j] = (orow && c < kend) ? wp[c] : 0.f;
            }
        }
    };
    auto stPW = [&](int buf) {
        *(float4*)&sP[buf][pc][(t & 15) * 4] = rp;
#pragma unroll
        for (int i = 0; i < 2; i++) {
            int id = t + 256 * i;
            int o  = id >> 2;
            int c4 = (id & 3) * 4;
#pragma unroll
            for (int j = 0; j < 4; j++) sW[buf][c4 + j][o] = rw[i * 4 + j];
        }
    };

    ldP(kbeg); ldW(kbeg);
    stPW(0);
    __syncthreads();
    int buf = 0;
    for (int k0 = kbeg; k0 < kend; k0 += 16) {
        bool nx = (k0 + 16) < kend;
        if (nx) { ldP(k0 + 16); ldW(k0 + 16); }
#pragma unroll
        for (int k = 0; k < 16; k++) {
            float4 a  = *(const float4*)&sP[buf][k][ty * 4];
            float4 b0 = *(const float4*)&sW[buf][k][tx * 4];
            float4 b1 = *(const float4*)&sW[buf][k][64 + tx * 4];
            float av[4] = {a.x, a.y, a.z, a.w};
            float bv[8] = {b0.x, b0.y, b0.z, b0.w, b1.x, b1.y, b1.z, b1.w};
#pragma unroll
            for (int i = 0; i < 4; i++)
#pragma unroll
                for (int j = 0; j < 8; j++)
                    acc[i][j] = fmaf(av[i], bv[j], acc[i][j]);
        }
        if (nx) stPW(buf ^ 1);
        __syncthreads();
        buf ^= 1;
    }
#pragma unroll
    for (int i = 0; i < 4; i++) {
        int n = n0 + ty * 4 + i;
#pragma unroll
        for (int j = 0; j < 8; j++) {
            int o = o0 + tx * 4 + (j & 3) + (j >> 2) * 64;
            if (o >= Mrows) continue;
            bool isA = (o < Cout);
            int  oi  = isA ? o : o - Cout;
            float v = acc[i][j];
            const float* ap = isA ? addA : addB;
            for (int s = 0; s < nAdd; s++)
                v += ap[(long)s * addstride + (long)n * Cout + oi];
            float* op = isA ? outA : outB;
            op[(long)si * osplit + (long)b * obatch + (long)n * on + (long)oi * oo] = v;
        }
    }
}

// ---------------------------------------------------------------------------
// bf16-split HMMA GEMM, cp.async double buffering, merged var+shared launch.
// z < zShared: var (b = z/S, si = z%S). z >= zShared: shared (b=0, si=z-zShared,
//   A offset +aShOff, B offset +bShOff, outputs outAs/outBs).
// Epilogue stages through smem for coalesced 512B stores.
__device__ __forceinline__ void mma16816(float* c, const uint32_t* a, const uint32_t* b)
{
    asm volatile("mma.sync.aligned.m16n8k16.row.col.f32.bf16.bf16.f32 "
        "{%0,%1,%2,%3}, {%4,%5,%6,%7}, {%8,%9}, {%0,%1,%2,%3};"
        : "+f"(c[0]), "+f"(c[1]), "+f"(c[2]), "+f"(c[3])
        : "r"(a[0]), "r"(a[1]), "r"(a[2]), "r"(a[3]), "r"(b[0]), "r"(b[1]));
}
#define HG_STAGE 40960      // 4 mats x 128 rows x 80B
#define HG_SMEM  (2 * HG_STAGE)

__global__ __launch_bounds__(256, 2)
void hgemm_kernel(const __nv_bfloat16* __restrict__ Ahi, const __nv_bfloat16* __restrict__ Alo,
                  int lda,
                  const __nv_bfloat16* __restrict__ Bhi, const __nv_bfloat16* __restrict__ Blo,
                  long bstride, int Cout, int S, int ksteps,
                  float* __restrict__ outA, float* __restrict__ outB,
                  long obstride, long osplit,
                  float* __restrict__ outAs, float* __restrict__ outBs,
                  long aShOff, long bShOff, int zShared, int mode)
{
    extern __shared__ __align__(128) char smem[];
    const int ldb = 4096;
    int t = threadIdx.x, w = t >> 5, l = t & 31;
    int z = blockIdx.z;
    bool shd = (z >= zShared);
    int zz = shd ? (z - zShared) : z;
    int b  = shd ? 0 : zz / S;
    int si = shd ? zz : (zz - b * S);
    int o0 = blockIdx.x * 128;
    int gy = blockIdx.y;
    int kbeg = si * ksteps * 32;

    long aoff = shd ? aShOff : 0;
    long boff = shd ? bShOff : (long)b * bstride;
    const __nv_bfloat16* aB[2] = {Ahi + aoff + (long)o0 * lda + kbeg,
                                  Alo + aoff + (long)o0 * lda + kbeg};
    const __nv_bfloat16* bB[2] = {Bhi + boff + (long)gy * 128 * ldb + kbeg,
                                  Blo + boff + (long)gy * 128 * ldb + kbeg};

    uint32_t sb0 = (uint32_t)__cvta_generic_to_shared(smem);
    int rowt = t >> 2, qt = t & 3;

    auto g2s = [&](int s, int ko) {
        uint32_t stg = sb0 + s * HG_STAGE;
#pragma unroll
        for (int h = 0; h < 2; h++)
#pragma unroll
            for (int i = 0; i < 2; i++) {
                int row = rowt + i * 64;
                uint32_t dA = stg + h * 10240 + row * 80 + qt * 16;
                const __nv_bfloat16* sA = aB[h] + (long)row * lda + ko + qt * 8;
                asm volatile("cp.async.cg.shared.global [%0], [%1], 16;" :: "r"(dA), "l"(sA));
                uint32_t dB = stg + 20480 + h * 10240 + row * 80 + qt * 16;
                const __nv_bfloat16* sB = bB[h] + (long)row * ldb + ko + qt * 8;
                asm volatile("cp.async.cg.shared.global [%0], [%1], 16;" :: "r"(dB), "l"(sB));
            }
        asm volatile("cp.async.commit_group;" ::: "memory");
    };

    float acc[2][8][4];
#pragma unroll
    for (int mt = 0; mt < 2; mt++)
#pragma unroll
        for (int j = 0; j < 8; j++)
#pragma unroll
            for (int c = 0; c < 4; c++) acc[mt][j][c] = 0.f;

    g2s(0, 0);
    if (ksteps > 1) g2s(1, 32);
    else            asm volatile("cp.async.commit_group;" ::: "memory");

    int wm = (w >> 1) * 32, wn = (w & 1) * 64;
    int lr = l >> 2, lc = (l & 3) * 4;

    for (int i = 0; i < ksteps; i++) {
        asm volatile("cp.async.wait_group 1;" ::: "memory");
        __syncthreads();
        char* stg = smem + (i & 1) * HG_STAGE;
#pragma unroll
        for (int kk = 0; kk < 2; kk++) {
            uint32_t af[2][2][4];
#pragma unroll
            for (int mt = 0; mt < 2; mt++)
#pragma unroll
                for (int h = 0; h < 2; h++) {
                    const char* base = stg + h * 10240 + (wm + mt * 16 + lr) * 80 + kk * 32 + lc;
                    af[mt][h][0] = *reinterpret_cast<const uint32_t*>(base);
                    af[mt][h][1] = *reinterpret_cast<const uint32_t*>(base + 8 * 80);
                    af[mt][h][2] = *reinterpret_cast<const uint32_t*>(base + 16);
                    af[mt][h][3] = *reinterpret_cast<const uint32_t*>(base + 8 * 80 + 16);
                }
            uint32_t bf[8][2][2];
#pragma unroll
            for (int j = 0; j < 8; j++)
#pragma unroll
                for (int h = 0; h < 2; h++) {
                    const char* base = stg + 20480 + h * 10240 + (wn + j * 8 + lr) * 80 + kk * 32 + lc;
                    bf[j][h][0] = *reinterpret_cast<const uint32_t*>(base);
                    bf[j][h][1] = *reinterpret_cast<const uint32_t*>(base + 16);
                }
#pragma unroll
            for (int mt = 0; mt < 2; mt++)
#pragma unroll
                for (int j = 0; j < 8; j++) {
                    mma16816(acc[mt][j], af[mt][0], bf[j][0]);
                    mma16816(acc[mt][j], af[mt][0], bf[j][1]);
                    mma16816(acc[mt][j], af[mt][1], bf[j][0]);
                }
        }
        __syncthreads();
        if (i + 2 < ksteps) g2s(i & 1, (i + 2) * 32);
        else                asm volatile("cp.async.commit_group;" ::: "memory");
    }

    // ---------------- epilogue: smem transpose for coalesced stores ----------
    asm volatile("cp.async.wait_group 0;" ::: "memory");
    __syncthreads();
    {
        float* so = reinterpret_cast<float*>(smem);   // [128][132] floats
#pragma unroll
        for (int mt = 0; mt < 2; mt++)
#pragma unroll
            for (int j = 0; j < 8; j++)
#pragma unroll
                for (int hf = 0; hf < 2; hf++) {
                    int ml = wm + mt * 16 + hf * 8 + lr;
                    int nl = wn + j * 8 + (l & 3) * 2;
#pragma unroll
                    for (int e = 0; e < 2; e++) {
                        float v = acc[mt][j][hf * 2 + e];
                        if (mode == 0) so[(nl + e) * 132 + ml] = v;   // [n][m]
                        else           so[ml * 132 + nl + e] = v;     // [m][n]
                    }
                }
    }
    __syncthreads();
    if (mode == 0) {
        bool isA = (o0 < Cout);
        int mo = isA ? o0 : o0 - Cout;
        float* oA = shd ? outAs : outA;
        float* oB = shd ? outBs : outB;
        float* outp = (isA ? oA : oB) + (long)si * osplit + (long)b * obstride;
        const float* so = reinterpret_cast<const float*>(smem);
#pragma unroll
        for (int it = 0; it < 16; it++) {
            int idx4 = it * 256 + t;
            int n  = idx4 >> 5;
            int mq = idx4 & 31;
            float4 v = *reinterpret_cast<const float4*>(so + n * 132 + mq * 4);
            long go = (long)(gy * 128 + n) * Cout + mo + mq * 4;
            *reinterpret_cast<float4*>(outp + go) = v;
        }
    } else {
        float* outp = (shd ? outAs : outA) + (long)zz * 65536;
        const float* so = reinterpret_cast<const float*>(smem);
#pragma unroll
        for (int it = 0; it < 16; it++) {
            int idx4 = it * 256 + t;
            int m  = idx4 >> 5;
            int nq = idx4 & 31;
            float4 v = *reinterpret_cast<const float4*>(so + m * 132 + nq * 4);
            *reinterpret_cast<float4*>(outp + (long)(o0 + m) * 256 + gy * 128 + nq * 4) = v;
        }
    }
}

// ---------------------------------------------------------------------------
// Gather (L0/L1, small Cout)
__global__ void gather_kernel(const float* __restrict__ A, const float* __restrict__ B2,
                              const int* __restrict__ idx, int Cout,
                              float* __restrict__ maxh, float* __restrict__ minh,
                              float* __restrict__ sumh, float* __restrict__ sumsq)
{
    int bn = blockIdx.y;
    int b  = bn >> 8;
    int o  = blockIdx.x * blockDim.x + threadIdx.x;
    if (o >= Cout) return;
    const int* ip = idx + (long)bn * KNN;
    long base = (long)bn * Cout + o;
    float an = A[base];
    float Cn = B2[base] - an;
    float mx = -3.4e38f, mn = 3.4e38f, s = 0.f, s2 = 0.f;
    long bbase = (long)(b * NPTS) * Cout + o;
#pragma unroll
    for (int k = 0; k < KNN; k++) {
        float v = A[bbase + (long)ip[k] * Cout];
        mx = fmaxf(mx, v); mn = fminf(mn, v); s += v; s2 += v * v;
    }
    maxh[base]  = mx + Cn;
    minh[base]  = mn + Cn;
    sumh[base]  = s + 27.f * Cn;
    sumsq[base] = s2 + 2.f * Cn * s + 27.f * Cn * Cn;
}

// ---------------------------------------------------------------------------
// Gather with smem-cached A tile + idx (L2/L3), fusing var+shared sums.
#define G2_SMEM (65536 + 27648 + 2048)
__global__ void gather2_kernel(const float* __restrict__ A, const float* __restrict__ B2,
                               const float* __restrict__ Ashr, const float* __restrict__ B2shr,
                               const int* __restrict__ idx, int Cout,
                               float* __restrict__ maxh, float* __restrict__ minh,
                               float* __restrict__ psum, float* __restrict__ psq)
{
    extern __shared__ float sm2[];
    float* sA  = sm2;                        // [256][64] floats
    int*   sI  = (int*)(sm2 + 16384);        // [256][27] ints
    float* red = sm2 + 16384 + 6912;         // [2][256] floats
    int b = blockIdx.y, o0 = blockIdx.x * 64, t = threadIdx.x;
    int ol = t & 63, ng = t >> 6;
    const float* Ab = A + (long)b * NPTS * Cout;
    for (int i = t; i < 16384; i += 256) {
        long gix = (long)(i >> 6) * Cout + o0 + (i & 63);
        sA[i] = Ab[gix] + Ashr[gix];
    }
    for (int i = t; i < 256 * KNN; i += 256)
        sI[i] = idx[(long)b * 256 * KNN + i];
    __syncthreads();
    float accs = 0.f, accs2 = 0.f;
    for (int n0 = 0; n0 < 256; n0 += 4) {
        int n = n0 + ng;
        const int* ip = sI + n * KNN;
        float mx = -3.4e38f, mn = 3.4e38f, s = 0.f, s2 = 0.f;
#pragma unroll
        for (int k = 0; k < KNN; k++) {
            float v = sA[ip[k] * 64 + ol];
            mx = fmaxf(mx, v); mn = fminf(mn, v); s += v; s2 += v * v;
        }
        float an = sA[n * 64 + ol];
        long sbase = (long)n * Cout + o0 + ol;
        long base  = (long)b * NPTS * Cout + sbase;
        float Cn = (B2[base] + B2shr[sbase]) - an;
        maxh[base] = mx + Cn;
        minh[base] = mn + Cn;
        accs  += s + 27.f * Cn;
        accs2 += s2 + 2.f * Cn * s + 27.f * Cn * Cn;
    }
    red[t] = accs; red[256 + t] = accs2;
    __syncthreads();
    if (ng == 0) {
        float S  = red[ol] + red[ol + 64] + red[ol + 128] + red[ol + 192];
        float S2 = red[256 + ol] + red[256 + ol + 64] + red[256 + ol + 128] + red[256 + ol + 192];
        psum[(long)b * Cout + o0 + ol] = S;
        psq [(long)b * Cout + o0 + ol] = S2;
    }
}

// ---------------------------------------------------------------------------
__global__ void stats_kernel(const float* __restrict__ sumh, const float* __restrict__ sumsq,
                             const float* __restrict__ g, const float* __restrict__ be,
                             int Cout, float* __restrict__ st)
{
    __shared__ float ss[256], ss2[256];
    int l  = threadIdx.x & 63;
    int gq = threadIdx.x >> 6;
    int o  = blockIdx.x * 64 + l;
    float s = 0.f, s2 = 0.f;
    if (o < Cout) {
        for (int bn = gq; bn < B4 * NPTS; bn += 4) {
            long ix = (long)bn * Cout + o;
            s += sumh[ix]; s2 += sumsq[ix];
        }
    }
    ss[threadIdx.x] = s; ss2[threadIdx.x] = s2;
    __syncthreads();
    if (gq == 0 && o < Cout) {
        double S  = (double)ss[l]  + ss[l + 64]  + ss[l + 128]  + ss[l + 192];
        double S2 = (double)ss2[l] + ss2[l + 64] + ss2[l + 128] + ss2[l + 192];
        const double invM = 1.0 / (double)(B4 * NPTS * KNN);
        double mean = S * invM;
        double var  = S2 * invM - mean * mean;
        float sc = g[o] * rsqrtf((float)var + 1e-5f);
        st[o] = sc;
        st[Cout + o] = be[o] - (float)mean * sc;
    }
}

// ---------------------------------------------------------------------------
__global__ void stats2_kernel(const float* __restrict__ ps, const float* __restrict__ pq,
                              const float* __restrict__ g, const float* __restrict__ be,
                              int Cout, float* __restrict__ st)
{
    int o = blockIdx.x * 256 + threadIdx.x;
    if (o >= Cout) return;
    double S = 0.0, S2 = 0.0;
    for (int b = 0; b < B4; b++) {
        S  += (double)ps[(long)b * Cout + o];
        S2 += (double)pq[(long)b * Cout + o];
    }
    const double invM = 1.0 / (double)(B4 * NPTS * KNN);
    double mean = S * invM;
    double var  = S2 * invM - mean * mean;
    float sc = g[o] * rsqrtf((float)var + 1e-5f);
    st[o] = sc;
    st[Cout + o] = be[o] - (float)mean * sc;
}

// ---------------------------------------------------------------------------
// affine+lrelu on k-extremum; bf16 hi/lo transposed outputs; fp32 opt (L0)
__global__ void finalize_kernel(const float* __restrict__ maxh, const float* __restrict__ minh,
                                const float* __restrict__ st, int Cout,
                                float* __restrict__ Xvar, float* __restrict__ Xsh,
                                int voff, int writeF32,
                                __nv_bfloat16* __restrict__ XvTh, __nv_bfloat16* __restrict__ XvTl,
                                __nv_bfloat16* __restrict__ XsTh, __nv_bfloat16* __restrict__ XsTl)
{
    __shared__ float T[B4][32][33];
    int o0 = blockIdx.x * 32, n0 = blockIdx.y * 32;
    int tx = threadIdx.x, ty = threadIdx.y;
    int o = o0 + tx;
    bool ov = (o < Cout);
    float sc = ov ? st[o] : 0.f;
    float tr = ov ? st[Cout + o] : 0.f;
    const float* src = (sc >= 0.f) ? maxh : minh;
    for (int r = ty; r < 32; r += 8) {
        int n = n0 + r;
        float vb[B4];
#pragma unroll
        for (int b = 0; b < B4; b++) {
            float vv = 0.f;
            if (ov) {
                float h = src[(long)(b * NPTS + n) * Cout + o];
                float yv = fmaf(sc, h, tr);
                vv = (yv >= 0.f) ? yv : 0.2f * yv;
            }
            vb[b] = vv;
            if (writeF32) T[b][r][tx] = vv;
        }
        if (ov) {
            int col = voff + o;
#pragma unroll
            for (int b = 0; b < B4; b++) {
                long ix = ((long)(b * 256 + n)) * 4096 + col;
                __nv_bfloat16 h = __float2bfloat16(vb[b]);
                XvTh[ix] = h;
                XvTl[ix] = __float2bfloat16(vb[b] - __bfloat162float(h));
            }
            float tp = 0.5f * (vb[0] + vb[1]);
            long ix2 = (long)n * 4096 + col;
            __nv_bfloat16 h2 = __float2bfloat16(tp);
            XsTh[ix2] = h2;
            XsTl[ix2] = __float2bfloat16(tp - __bfloat162float(h2));
        }
    }
    if (writeF32) {
        __syncthreads();
        for (int r = ty; r < 32; r += 8) {
            int oc = o0 + r;
            if (oc < Cout) {
                int n = n0 + tx;
                float tp = 0.5f * (T[0][tx][r] + T[1][tx][r]);
#pragma unroll
                for (int b = 0; b < B4; b++)
                    Xvar[((long)b * 64 + voff + oc) * NPTS + n] = T[b][tx][r];
                Xsh[(long)(voff + oc) * NPTS + n] = tp;
            }
        }
    }
}

// ---------------------------------------------------------------------------
__global__ void final_bn_kernel(const float* __restrict__ ypv, const float* __restrict__ yps,
                                const float* __restrict__ g, const float* __restrict__ be,
                                float* __restrict__ out)
{
    int o = blockIdx.x, t = threadIdx.x;
    float sh = 0.f;
#pragma unroll
    for (int sp = 0; sp < 8; sp++) sh += yps[(long)sp * 65536 + o * 256 + t];
    float v[B4];
    float s = 0.f, s2 = 0.f;
#pragma unroll
    for (int b = 0; b < B4; b++) {
        float xv = sh;
#pragma unroll
        for (int sp = 0; sp < 8; sp++)
            xv += ypv[(long)(b * 8 + sp) * 65536 + o * 256 + t];
        v[b] = xv; s += xv; s2 += xv * xv;
    }
    __shared__ float rs[256], rs2[256];
    rs[t] = s; rs2[t] = s2;
    __syncthreads();
    for (int off = 128; off > 0; off >>= 1) {
        if (t < off) { rs[t] += rs[t + off]; rs2[t] += rs2[t + off]; }
        __syncthreads();
    }
    float mean = rs[0] * (1.f / 1024.f);
    float var  = rs2[0] * (1.f / 1024.f) - mean * mean;
    float sc = g[o] * rsqrtf(var + 1e-5f);
    float tr = be[o] - mean * sc;
#pragma unroll
    for (int b = 0; b < B4; b++) {
        float yv = fmaf(sc, v[b], tr);
        out[(long)b * 65536 + o * 256 + t] = (yv >= 0.f) ? yv : 0.2f * yv;
    }
}

// ---------------------------------------------------------------------------
extern "C" void kernel_launch(void* const* d_in, const int* in_sizes, int n_in,
                              void* d_out, int out_size)
{
    const float* x = (const float*)d_in[0];
    const float* w[5]  = {(const float*)d_in[1], (const float*)d_in[4], (const float*)d_in[7],
                          (const float*)d_in[10], (const float*)d_in[13]};
    const float* gm[5] = {(const float*)d_in[2], (const float*)d_in[5], (const float*)d_in[8],
                          (const float*)d_in[11], (const float*)d_in[14]};
    const float* bt[5] = {(const float*)d_in[3], (const float*)d_in[6], (const float*)d_in[9],
                          (const float*)d_in[12], (const float*)d_in[15]};
    float* out = (float*)d_out;

    float *pA, *pB2, *pAs, *pBs, *pMax, *pMin, *pSum, *pSq;
    float *pXv, *pXs, *pYpv, *pYps, *pSt, *pP0;
    __nv_bfloat16 *pAhi, *pAlo, *pBhi, *pBlo;
    int* pIdx;
    cudaGetSymbolAddress((void**)&pA, g_A);
    cudaGetSymbolAddress((void**)&pB2, g_B2);
    cudaGetSymbolAddress((void**)&pAs, g_Ash);
    cudaGetSymbolAddress((void**)&pBs, g_Bsh);
    cudaGetSymbolAddress((void**)&pMax, g_maxh);
    cudaGetSymbolAddress((void**)&pMin, g_minh);
    cudaGetSymbolAddress((void**)&pSum, g_sumh);
    cudaGetSymbolAddress((void**)&pSq, g_sumsq);
    cudaGetSymbolAddress((void**)&pXv, g_Xvar);
    cudaGetSymbolAddress((void**)&pXs, g_Xsh);
    cudaGetSymbolAddress((void**)&pYpv, g_ypv);
    cudaGetSymbolAddress((void**)&pYps, g_yps);
    cudaGetSymbolAddress((void**)&pSt, g_st);
    cudaGetSymbolAddress((void**)&pP0, g_P0);
    cudaGetSymbolAddress((void**)&pIdx, g_idx);
    cudaGetSymbolAddress((void**)&pAhi, g_Ahi);
    cudaGetSymbolAddress((void**)&pAlo, g_Alo);
    cudaGetSymbolAddress((void**)&pBhi, g_Bhi);
    cudaGetSymbolAddress((void**)&pBlo, g_Blo);

    cudaFuncSetAttribute(hgemm_kernel, cudaFuncAttributeMaxDynamicSharedMemorySize, HG_SMEM);
    cudaFuncSetAttribute(gather2_kernel, cudaFuncAttributeMaxDynamicSharedMemorySize, G2_SMEM);

    xpose_kernel<<<12, 256>>>(x, pP0);
    knn_kernel<<<dim3(32, B4), 256>>>(x, pIdx);
    wsplit_kernel<<<dim3(1, 384), 256>>>(w[2], 768, 192,
        pAhi + AV2, pAlo + AV2, pAhi + ASH2, pAlo + ASH2);
    wsplit_kernel<<<dim3(3, 1536), 256>>>(w[3], 3072, 768,
        pAhi + AV3, pAlo + AV3, pAhi + ASH3, pAlo + ASH3);
    w4split_kernel<<<4096, 256>>>(w[4],
        pAhi + W4V, pAlo + W4V, pAhi + W4S, pAlo + W4S);

    // ---- L0 (SIMT, K=3) ----
    gemm_kernel<<<dim3(1, 4, B4), 256>>>(pP0, 768, w[0], 6, 0, 3, 48, 96, 3,
        nullptr, nullptr, 0, 0, pA, pB2, 0, (long)NPTS * 48, 48, 1, 1, 16);
    gather_kernel<<<dim3(1, B4 * NPTS), 256>>>(pA, pB2, pIdx, 48, pMax, pMin, pSum, pSq);
    stats_kernel<<<1, 256>>>(pSum, pSq, gm[0], bt[0], 48, pSt);
    finalize_kernel<<<dim3(2, 8), dim3(32, 8)>>>(pMax, pMin, pSt, 48, pXv, pXs, 0, 1,
        pBhi + XV, pBlo + XV, pBhi + XSH, pBlo + XSH);

    // ---- L1 (SIMT, K=48) ----
    gemm_kernel<<<dim3(3, 4, 1), 256>>>(pXs, 0, w[1], 192, 48, 144, 192, 384, 48,
        nullptr, nullptr, 0, 0, pAs, pBs, 0, 0, 192, 1, 1, 48);
    gemm_kernel<<<dim3(3, 4, B4), 256>>>(pXv, (long)64 * NPTS, w[1], 192, 0, 96, 192, 384, 48,
        pAs, pBs, 1, 0, pA, pB2, 0, (long)NPTS * 192, 192, 1, 1, 48);
    gather_kernel<<<dim3(1, B4 * NPTS), 256>>>(pA, pB2, pIdx, 192, pMax, pMin, pSum, pSq);
    stats_kernel<<<3, 256>>>(pSum, pSq, gm[1], bt[1], 192, pSt);
    finalize_kernel<<<dim3(6, 8), dim3(32, 8)>>>(pMax, pMin, pSt, 192, pXv, pXs, 48, 0,
        pBhi + XV, pBlo + XV, pBhi + XSH, pBlo + XSH);

    // ---- L2 (HMMA, K=192): merged var(z 0-3) + shared(z 4) ----
    hgemm_kernel<<<dim3(12, 2, 5), 256, HG_SMEM>>>(pAhi + AV2, pAlo + AV2, 192,
        pBhi + XV + 48, pBlo + XV + 48, 1048576, 768, 1, 6,
        pA, pB2, (long)NPTS * 768, 0,
        pAs, pBs, ASH2 - AV2, XSH - XV, 4, 0);
    gather2_kernel<<<dim3(12, B4), 256, G2_SMEM>>>(pA, pB2, pAs, pBs, pIdx, 768,
        pMax, pMin, pSum, pSq);
    stats2_kernel<<<3, 256>>>(pSum, pSq, gm[2], bt[2], 768, pSt);
    finalize_kernel<<<dim3(24, 8), dim3(32, 8)>>>(pMax, pMin, pSt, 768, pXv, pXs, 240, 0,
        pBhi + XV, pBlo + XV, pBhi + XSH, pBlo + XSH);

    // ---- L3 (HMMA, K=768): merged var(z 0-3) + shared(z 4) ----
    hgemm_kernel<<<dim3(48, 2, 5), 256, HG_SMEM>>>(pAhi + AV3, pAlo + AV3, 768,
        pBhi + XV + 240, pBlo + XV + 240, 1048576, 3072, 1, 24,
        pA, pB2, (long)NPTS * 3072, 0,
        pAs, pBs, ASH3 - AV3, XSH - XV, 4, 0);
    gather2_kernel<<<dim3(48, B4), 256, G2_SMEM>>>(pA, pB2, pAs, pBs, pIdx, 3072,
        pMax, pMin, pSum, pSq);
    stats2_kernel<<<12, 256>>>(pSum, pSq, gm[3], bt[3], 3072, pSt);
    finalize_kernel<<<dim3(96, 8), dim3(32, 8)>>>(pMax, pMin, pSt, 3072, pXv, pXs, 1008, 0,
        pBhi + XV, pBlo + XV, pBhi + XSH, pBlo + XSH);

    // ---- final projection (HMMA, K=4096, split-K=8): merged var(z 0-31) + shared(z 32-39) ----
    hgemm_kernel<<<dim3(2, 2, 40), 256, HG_SMEM>>>(pAhi + W4V, pAlo + W4V, 4096,
        pBhi + XV, pBlo + XV, 1048576, 256, 8, 16,
        pYpv, pYpv, 0, 0,
        pYps, pYps, W4S - W4V, XSH - XV, 32, 1);
    final_bn_kernel<<<256, 256>>>(pYpv, pYps, gm[4], bt[4], out);
}

// round 14
// speedup vs baseline: 1.0377x; 1.0377x over previous
#include <cuda_runtime.h>
#include <cuda_bf16.h>
#include <cstdint>

#define B4    4
#define NPTS  256
#define KNN   27
#define MAXC  3072
#define VTOT  4080
// bf16 A-pool offsets (elements)
#define AV2   0L
#define ASH2  294912L
#define AV3   589824L
#define ASH3  5308416L
#define W4V   10027008L
#define W4S   11075584L
#define ABFN  12124160L
// bf16 B-pool offsets
#define XV    0L
#define XSH   4194304L
#define BBFN  5242880L

__device__ __align__(256) float g_A    [B4 * NPTS * MAXC];
__device__ __align__(256) float g_B2   [B4 * NPTS * MAXC];
__device__ __align__(256) float g_Ash  [2 * NPTS * MAXC];
__device__ __align__(256) float g_Bsh  [2 * NPTS * MAXC];
__device__ __align__(256) float g_maxh [B4 * NPTS * MAXC];
__device__ __align__(256) float g_minh [B4 * NPTS * MAXC];
__device__ __align__(256) float g_sumh [B4 * NPTS * MAXC];
__device__ __align__(256) float g_sumsq[B4 * NPTS * MAXC];
__device__ __align__(256) float g_Xvar [B4 * 64 * NPTS];     // fp32 L0 out only
__device__ __align__(256) float g_Xsh  [64 * NPTS];
__device__ __align__(256) float g_ypv  [32 * 256 * NPTS];
__device__ __align__(256) float g_yps  [8 * 256 * NPTS];
__device__ __align__(256) float g_st   [2 * MAXC];
__device__ __align__(256) float g_P0   [B4 * 3 * NPTS];
__device__ __align__(256) int   g_idx  [B4 * NPTS * KNN];
__device__ __align__(256) __nv_bfloat16 g_Ahi[ABFN];
__device__ __align__(256) __nv_bfloat16 g_Alo[ABFN];
__device__ __align__(256) __nv_bfloat16 g_Bhi[BBFN];
__device__ __align__(256) __nv_bfloat16 g_Blo[BBFN];

// ---------------------------------------------------------------------------
__global__ void xpose_kernel(const float* __restrict__ x, float* __restrict__ P0)
{
    int id = blockIdx.x * 256 + threadIdx.x;
    if (id >= B4 * 3 * NPTS) return;
    int b = id / (3 * NPTS), r = id % (3 * NPTS);
    P0[id] = x[((long)b * NPTS + (r % NPTS)) * 3 + (r / NPTS)];
}

// ---------------------------------------------------------------------------
__global__ void knn_kernel(const float* __restrict__ x, int* __restrict__ idxout)
{
    __shared__ float px[NPTS], py[NPTS], pz[NPTS];
    int b = blockIdx.y, t = threadIdx.x;
    int w = t >> 5, lane = t & 31;
    {
        const float* xb = x + (long)b * NPTS * 3;
        px[t] = xb[t * 3 + 0]; py[t] = xb[t * 3 + 1]; pz[t] = xb[t * 3 + 2];
    }
    __syncthreads();
    int i = blockIdx.x * 8 + w;
    float xi = px[i], yi = py[i], zi = pz[i];
    float d[8];
#pragma unroll
    for (int m = 0; m < 8; m++) {
        int j = lane + 32 * m;
        float dx = xi - px[j], dy = yi - py[j], dz = zi - pz[j];
        d[m] = __fadd_rn(__fadd_rn(__fmul_rn(dx, dx), __fmul_rn(dy, dy)), __fmul_rn(dz, dz));
    }
    for (int k = 0; k < KNN; k++) {
        float bv = d[0]; int bm = 0;
#pragma unroll
        for (int m = 1; m < 8; m++) if (d[m] < bv) { bv = d[m]; bm = m; }
        int bj = lane + 32 * bm;
#pragma unroll
        for (int off = 16; off > 0; off >>= 1) {
            float ov = __shfl_down_sync(0xffffffffu, bv, off);
            int   oj = __shfl_down_sync(0xffffffffu, bj, off);
            if (ov < bv || (ov == bv && oj < bj)) { bv = ov; bj = oj; }
        }
        bj = __shfl_sync(0xffffffffu, bj, 0);
        if (lane == 0) idxout[((long)b * NPTS + i) * KNN + k] = bj;
        if ((bj & 31) == lane) {
            int m = bj >> 5;
#pragma unroll
            for (int mm = 0; mm < 8; mm++) if (mm == m) d[mm] = 3.4e38f;
        }
    }
}

// ---------------------------------------------------------------------------
// Vectorized, division-free weight split; 2 rows per thread.
// grid: (ceil(Cp/256), Cout/2).
__global__ void wsplit_kernel(const float* __restrict__ w, int Cout, int Cp,
                              __nv_bfloat16* __restrict__ Avh, __nv_bfloat16* __restrict__ Avl,
                              __nv_bfloat16* __restrict__ Ash, __nv_bfloat16* __restrict__ Asl)
{
    int c4 = blockIdx.x * 256 + threadIdx.x;
    if (c4 >= Cp) return;
    int Cp4 = Cp >> 2;
    int q = (c4 >= Cp4) + (c4 >= 2 * Cp4) + (c4 >= 3 * Cp4);
    int k4 = c4 - q * Cp4;
    __nv_bfloat16* ph = ((q & 1) == 0) ? Avh : Ash;
    __nv_bfloat16* pl = ((q & 1) == 0) ? Avl : Asl;
    float4 vv[2];
#pragma unroll
    for (int r = 0; r < 2; r++) {
        int m = blockIdx.y * 2 + r;
        vv[r] = reinterpret_cast<const float4*>(w)[(long)m * Cp + c4];
    }
#pragma unroll
    for (int r = 0; r < 2; r++) {
        int m = blockIdx.y * 2 + r;
        float4 v = vv[r];
        __nv_bfloat16 hx = __float2bfloat16(v.x), hy = __float2bfloat16(v.y);
        __nv_bfloat16 hz = __float2bfloat16(v.z), hw = __float2bfloat16(v.w);
        __nv_bfloat16 lx = __float2bfloat16(v.x - __bfloat162float(hx));
        __nv_bfloat16 ly = __float2bfloat16(v.y - __bfloat162float(hy));
        __nv_bfloat16 lz = __float2bfloat16(v.z - __bfloat162float(hz));
        __nv_bfloat16 lw = __float2bfloat16(v.w - __bfloat162float(hw));
        long dst = (long)((q >= 2) ? m + Cout : m) * Cp + k4 * 4;
        *reinterpret_cast<__nv_bfloat162*>(ph + dst)     = __halves2bfloat162(hx, hy);
        *reinterpret_cast<__nv_bfloat162*>(ph + dst + 2) = __halves2bfloat162(hz, hw);
        *reinterpret_cast<__nv_bfloat162*>(pl + dst)     = __halves2bfloat162(lx, ly);
        *reinterpret_cast<__nv_bfloat162*>(pl + dst + 2) = __halves2bfloat162(lz, lw);
    }
}

// ---------------------------------------------------------------------------
__global__ void w4split_kernel(const float* __restrict__ w4,
                               __nv_bfloat16* __restrict__ Avh, __nv_bfloat16* __restrict__ Avl,
                               __nv_bfloat16* __restrict__ Ash, __nv_bfloat16* __restrict__ Asl)
{
    int id = blockIdx.x * 256 + threadIdx.x;
    if (id >= 256 * 4096) return;
    int o = id >> 12, vc = id & 4095;
    float vv = 0.f, vs = 0.f;
    if (vc < VTOT) {
        int CL, off4, voff;
        if (vc < 48)        { CL = 48;   off4 = 0;    voff = 0;    }
        else if (vc < 240)  { CL = 192;  off4 = 96;   voff = 48;   }
        else if (vc < 1008) { CL = 768;  off4 = 480;  voff = 240;  }
        else                { CL = 3072; off4 = 2016; voff = 1008; }
        int c = vc - voff;
        vv = w4[(long)o * 8160 + off4 + c];
        vs = w4[(long)o * 8160 + off4 + CL + c];
    }
    __nv_bfloat16 h1 = __float2bfloat16(vv);
    Avh[id] = h1; Avl[id] = __float2bfloat16(vv - __bfloat162float(h1));
    __nv_bfloat16 h2 = __float2bfloat16(vs);
    Ash[id] = h2; Asl[id] = __float2bfloat16(vs - __bfloat162float(h2));
}

// ---------------------------------------------------------------------------
// SIMT GEMM for layers 0-1 (proven R2 version)
__global__ __launch_bounds__(256, 2)
void gemm_kernel(const float* __restrict__ P, long pstride,
                 const float* __restrict__ W, int ldw, int coffA, int coffB,
                 int Cout, int Mrows, int Kc,
                 const float* __restrict__ addA, const float* __restrict__ addB,
                 int nAdd, long addstride,
                 float* __restrict__ outA, float* __restrict__ outB,
                 long osplit, long obatch, long on, long oo,
                 int S, int kchunk)
{
    int z  = blockIdx.z;
    int b  = z / S, si = z - b * S;
    int kbeg = si * kchunk;
    int kend = min(Kc, kbeg + kchunk);
    int o0 = blockIdx.x * 128, n0 = blockIdx.y * 64;
    int t  = threadIdx.x;
    int tx = t & 15, ty = t >> 4;

    __shared__ float sP[2][16][68];
    __shared__ float sW[2][16][132];

    float acc[4][8];
#pragma unroll
    for (int i = 0; i < 4; i++)
#pragma unroll
        for (int j = 0; j < 8; j++) acc[i][j] = 0.f;

    const float* Pb = P + (long)b * pstride;
    int pc = t >> 4;
    int pn = n0 + (t & 15) * 4;
    float4 rp;
    float  rw[8];

    auto ldP = [&](int k0) {
        int c = k0 + pc;
        if (c < kend) rp = *(const float4*)(Pb + (long)c * NPTS + pn);
        else          rp = make_float4(0.f, 0.f, 0.f, 0.f);
    };
    auto ldW = [&](int k0) {
#pragma unroll
        for (int i = 0; i < 2; i++) {
            int id = t + 256 * i;
            int o  = o0 + (id >> 2);
            int c4 = (id & 3) * 4;
            bool orow = (o < Mrows);
            const float* wp = W + (orow ?
                ((long)((o < Cout) ? o : (o - Cout)) * ldw + ((o < Cout) ? coffA : coffB)) : 0);
#pragma unroll
            for (int j = 0; j < 4; j++) {
                int c = k0 + c4 + j;
                rw[i * 4 + j] = (orow && c < kend) ? wp[c] : 0.f;
            }
        }
    };
    auto stPW = [&](int buf) {
        *(float4*)&sP[buf][pc][(t & 15) * 4] = rp;
#pragma unroll
        for (int i = 0; i < 2; i++) {
            int id = t + 256 * i;
            int o  = id >> 2;
            int c4 = (id & 3) * 4;
#pragma unroll
            for (int j = 0; j < 4; j++) sW[buf][c4 + j][o] = rw[i * 4 + j];
        }
    };

    ldP(kbeg); ldW(kbeg);
    stPW(0);
    __syncthreads();
    int buf = 0;
    for (int k0 = kbeg; k0 < kend; k0 += 16) {
        bool nx = (k0 + 16) < kend;
        if (nx) { ldP(k0 + 16); ldW(k0 + 16); }
#pragma unroll
        for (int k = 0; k < 16; k++) {
            float4 a  = *(const float4*)&sP[buf][k][ty * 4];
            float4 b0 = *(const float4*)&sW[buf][k][tx * 4];
            float4 b1 = *(const float4*)&sW[buf][k][64 + tx * 4];
            float av[4] = {a.x, a.y, a.z, a.w};
            float bv[8] = {b0.x, b0.y, b0.z, b0.w, b1.x, b1.y, b1.z, b1.w};
#pragma unroll
            for (int i = 0; i < 4; i++)
#pragma unroll
                for (int j = 0; j < 8; j++)
                    acc[i][j] = fmaf(av[i], bv[j], acc[i][j]);
        }
        if (nx) stPW(buf ^ 1);
        __syncthreads();
        buf ^= 1;
    }
#pragma unroll
    for (int i = 0; i < 4; i++) {
        int n = n0 + ty * 4 + i;
#pragma unroll
        for (int j = 0; j < 8; j++) {
            int o = o0 + tx * 4 + (j & 3) + (j >> 2) * 64;
            if (o >= Mrows) continue;
            bool isA = (o < Cout);
            int  oi  = isA ? o : o - Cout;
            float v = acc[i][j];
            const float* ap = isA ? addA : addB;
            for (int s = 0; s < nAdd; s++)
                v += ap[(long)s * addstride + (long)n * Cout + oi];
            float* op = isA ? outA : outB;
            op[(long)si * osplit + (long)b * obatch + (long)n * on + (long)oi * oo] = v;
        }
    }
}

// ---------------------------------------------------------------------------
// bf16-split HMMA GEMM, cp.async double buffering (R10 proven version).
// Epilogue stages through smem for coalesced 512B stores; mode0 adds partials.
__device__ __forceinline__ void mma16816(float* c, const uint32_t* a, const uint32_t* b)
{
    asm volatile("mma.sync.aligned.m16n8k16.row.col.f32.bf16.bf16.f32 "
        "{%0,%1,%2,%3}, {%4,%5,%6,%7}, {%8,%9}, {%0,%1,%2,%3};"
        : "+f"(c[0]), "+f"(c[1]), "+f"(c[2]), "+f"(c[3])
        : "r"(a[0]), "r"(a[1]), "r"(a[2]), "r"(a[3]), "r"(b[0]), "r"(b[1]));
}
#define HG_STAGE 40960      // 4 mats x 128 rows x 80B
#define HG_SMEM  (2 * HG_STAGE)

__global__ __launch_bounds__(256, 2)
void hgemm_kernel(const __nv_bfloat16* __restrict__ Ahi, const __nv_bfloat16* __restrict__ Alo,
                  int lda,
                  const __nv_bfloat16* __restrict__ Bhi, const __nv_bfloat16* __restrict__ Blo,
                  long bstride, int Cout, int S, int ksteps,
                  float* __restrict__ outA, float* __restrict__ outB,
                  long obstride, long osplit,
                  const float* __restrict__ addA, const float* __restrict__ addB,
                  int nAdd, long addstride, int mode)
{
    extern __shared__ __align__(128) char smem[];
    const int ldb = 4096;
    int t = threadIdx.x, w = t >> 5, l = t & 31;
    int z = blockIdx.z, b = z / S, si = z - b * S;
    int o0 = blockIdx.x * 128;
    int gy = blockIdx.y;
    int kbeg = si * ksteps * 32;

    const __nv_bfloat16* aB[2] = {Ahi + (long)o0 * lda + kbeg, Alo + (long)o0 * lda + kbeg};
    const __nv_bfloat16* bB[2] = {Bhi + (long)b * bstride + (long)gy * 128 * ldb + kbeg,
                                  Blo + (long)b * bstride + (long)gy * 128 * ldb + kbeg};

    uint32_t sb0 = (uint32_t)__cvta_generic_to_shared(smem);
    int rowt = t >> 2, qt = t & 3;

    auto g2s = [&](int s, int ko) {
        uint32_t stg = sb0 + s * HG_STAGE;
#pragma unroll
        for (int h = 0; h < 2; h++)
#pragma unroll
            for (int i = 0; i < 2; i++) {
                int row = rowt + i * 64;
                uint32_t dA = stg + h * 10240 + row * 80 + qt * 16;
                const __nv_bfloat16* sA = aB[h] + (long)row * lda + ko + qt * 8;
                asm volatile("cp.async.cg.shared.global [%0], [%1], 16;" :: "r"(dA), "l"(sA));
                uint32_t dB = stg + 20480 + h * 10240 + row * 80 + qt * 16;
                const __nv_bfloat16* sB = bB[h] + (long)row * ldb + ko + qt * 8;
                asm volatile("cp.async.cg.shared.global [%0], [%1], 16;" :: "r"(dB), "l"(sB));
            }
        asm volatile("cp.async.commit_group;" ::: "memory");
    };

    float acc[2][8][4];
#pragma unroll
    for (int mt = 0; mt < 2; mt++)
#pragma unroll
        for (int j = 0; j < 8; j++)
#pragma unroll
            for (int c = 0; c < 4; c++) acc[mt][j][c] = 0.f;

    g2s(0, 0);
    if (ksteps > 1) g2s(1, 32);
    else            asm volatile("cp.async.commit_group;" ::: "memory");

    int wm = (w >> 1) * 32, wn = (w & 1) * 64;
    int lr = l >> 2, lc = (l & 3) * 4;

    for (int i = 0; i < ksteps; i++) {
        asm volatile("cp.async.wait_group 1;" ::: "memory");
        __syncthreads();
        char* stg = smem + (i & 1) * HG_STAGE;
#pragma unroll
        for (int kk = 0; kk < 2; kk++) {
            uint32_t af[2][2][4];
#pragma unroll
            for (int mt = 0; mt < 2; mt++)
#pragma unroll
                for (int h = 0; h < 2; h++) {
                    const char* base = stg + h * 10240 + (wm + mt * 16 + lr) * 80 + kk * 32 + lc;
                    af[mt][h][0] = *reinterpret_cast<const uint32_t*>(base);
                    af[mt][h][1] = *reinterpret_cast<const uint32_t*>(base + 8 * 80);
                    af[mt][h][2] = *reinterpret_cast<const uint32_t*>(base + 16);
                    af[mt][h][3] = *reinterpret_cast<const uint32_t*>(base + 8 * 80 + 16);
                }
            uint32_t bf[8][2][2];
#pragma unroll
            for (int j = 0; j < 8; j++)
#pragma unroll
                for (int h = 0; h < 2; h++) {
                    const char* base = stg + 20480 + h * 10240 + (wn + j * 8 + lr) * 80 + kk * 32 + lc;
                    bf[j][h][0] = *reinterpret_cast<const uint32_t*>(base);
                    bf[j][h][1] = *reinterpret_cast<const uint32_t*>(base + 16);
                }
#pragma unroll
            for (int mt = 0; mt < 2; mt++)
#pragma unroll
                for (int j = 0; j < 8; j++) {
                    mma16816(acc[mt][j], af[mt][0], bf[j][0]);
                    mma16816(acc[mt][j], af[mt][0], bf[j][1]);
                    mma16816(acc[mt][j], af[mt][1], bf[j][0]);
                }
        }
        __syncthreads();
        if (i + 2 < ksteps) g2s(i & 1, (i + 2) * 32);
        else                asm volatile("cp.async.commit_group;" ::: "memory");
    }

    // ---------------- epilogue: smem transpose for coalesced stores ----------
    asm volatile("cp.async.wait_group 0;" ::: "memory");
    __syncthreads();
    {
        float* so = reinterpret_cast<float*>(smem);   // [128][132] floats
#pragma unroll
        for (int mt = 0; mt < 2; mt++)
#pragma unroll
            for (int j = 0; j < 8; j++)
#pragma unroll
                for (int hf = 0; hf < 2; hf++) {
                    int ml = wm + mt * 16 + hf * 8 + lr;
                    int nl = wn + j * 8 + (l & 3) * 2;
#pragma unroll
                    for (int e = 0; e < 2; e++) {
                        float v = acc[mt][j][hf * 2 + e];
                        if (mode == 0) so[(nl + e) * 132 + ml] = v;   // [n][m]
                        else           so[ml * 132 + nl + e] = v;     // [m][n]
                    }
                }
    }
    __syncthreads();
    if (mode == 0) {
        bool isA = (o0 < Cout);
        int mo = isA ? o0 : o0 - Cout;
        float* outp = (isA ? outA : outB) + (long)si * osplit + (long)b * obstride;
        const float* ad = nAdd ? (isA ? addA : addB) : nullptr;
        const float* so = reinterpret_cast<const float*>(smem);
#pragma unroll
        for (int it = 0; it < 16; it++) {
            int idx4 = it * 256 + t;
            int n  = idx4 >> 5;
            int mq = idx4 & 31;
            float4 v = *reinterpret_cast<const float4*>(so + n * 132 + mq * 4);
            long go = (long)(gy * 128 + n) * Cout + mo + mq * 4;
            for (int s = 0; s < nAdd; s++) {
                float4 a4 = *reinterpret_cast<const float4*>(ad + (long)s * addstride + go);
                v.x += a4.x; v.y += a4.y; v.z += a4.z; v.w += a4.w;
            }
            *reinterpret_cast<float4*>(outp + go) = v;
        }
    } else {
        float* outp = outA + (long)z * 65536;
        const float* so = reinterpret_cast<const float*>(smem);
#pragma unroll
        for (int it = 0; it < 16; it++) {
            int idx4 = it * 256 + t;
            int m  = idx4 >> 5;
            int nq = idx4 & 31;
            float4 v = *reinterpret_cast<const float4*>(so + m * 132 + nq * 4);
            *reinterpret_cast<float4*>(outp + (long)(o0 + m) * 256 + gy * 128 + nq * 4) = v;
        }
    }
}

// ---------------------------------------------------------------------------
// Gather (L0/L1, small Cout)
__global__ void gather_kernel(const float* __restrict__ A, const float* __restrict__ B2,
                              const int* __restrict__ idx, int Cout,
                              float* __restrict__ maxh, float* __restrict__ minh,
                              float* __restrict__ sumh, float* __restrict__ sumsq)
{
    int bn = blockIdx.y;
    int b  = bn >> 8;
    int o  = blockIdx.x * blockDim.x + threadIdx.x;
    if (o >= Cout) return;
    const int* ip = idx + (long)bn * KNN;
    long base = (long)bn * Cout + o;
    float an = A[base];
    float Cn = B2[base] - an;
    float mx = -3.4e38f, mn = 3.4e38f, s = 0.f, s2 = 0.f;
    long bbase = (long)(b * NPTS) * Cout + o;
#pragma unroll
    for (int k = 0; k < KNN; k++) {
        float v = A[bbase + (long)ip[k] * Cout];
        mx = fmaxf(mx, v); mn = fminf(mn, v); s += v; s2 += v * v;
    }
    maxh[base]  = mx + Cn;
    minh[base]  = mn + Cn;
    sumh[base]  = s + 27.f * Cn;
    sumsq[base] = s2 + 2.f * Cn * s + 27.f * Cn * Cn;
}

// ---------------------------------------------------------------------------
// Gather with smem-cached A tile + idx (L2/L3). R10 proven version.
#define G2_SMEM (65536 + 27648 + 2048)
__global__ void gather2_kernel(const float* __restrict__ A, const float* __restrict__ B2,
                               const int* __restrict__ idx, int Cout,
                               float* __restrict__ maxh, float* __restrict__ minh,
                               float* __restrict__ psum, float* __restrict__ psq)
{
    extern __shared__ float sm2[];
    float* sA  = sm2;                        // [256][64] floats
    int*   sI  = (int*)(sm2 + 16384);        // [256][27] ints
    float* red = sm2 + 16384 + 6912;         // [2][256] floats
    int b = blockIdx.y, o0 = blockIdx.x * 64, t = threadIdx.x;
    int ol = t & 63, ng = t >> 6;
    const float* Ab = A + (long)b * NPTS * Cout;
    for (int i = t; i < 16384; i += 256)
        sA[i] = Ab[(long)(i >> 6) * Cout + o0 + (i & 63)];
    for (int i = t; i < 256 * KNN; i += 256)
        sI[i] = idx[(long)b * 256 * KNN + i];
    __syncthreads();
    float accs = 0.f, accs2 = 0.f;
    for (int n0 = 0; n0 < 256; n0 += 4) {
        int n = n0 + ng;
        const int* ip = sI + n * KNN;
        float mx = -3.4e38f, mn = 3.4e38f, s = 0.f, s2 = 0.f;
#pragma unroll
        for (int k = 0; k < KNN; k++) {
            float v = sA[ip[k] * 64 + ol];
            mx = fmaxf(mx, v); mn = fminf(mn, v); s += v; s2 += v * v;
        }
        float an = sA[n * 64 + ol];
        long base = ((long)(b * 256 + n)) * Cout + o0 + ol;
        float Cn = B2[base] - an;
        maxh[base] = mx + Cn;
        minh[base] = mn + Cn;
        accs  += s + 27.f * Cn;
        accs2 += s2 + 2.f * Cn * s + 27.f * Cn * Cn;
    }
    red[t] = accs; red[256 + t] = accs2;
    __syncthreads();
    if (ng == 0) {
        float S  = red[ol] + red[ol + 64] + red[ol + 128] + red[ol + 192];
        float S2 = red[256 + ol] + red[256 + ol + 64] + red[256 + ol + 128] + red[256 + ol + 192];
        psum[(long)b * Cout + o0 + ol] = S;
        psq [(long)b * Cout + o0 + ol] = S2;
    }
}

// ---------------------------------------------------------------------------
__global__ void stats_kernel(const float* __restrict__ sumh, const float* __restrict__ sumsq,
                             const float* __restrict__ g, const float* __restrict__ be,
                             int Cout, float* __restrict__ st)
{
    __shared__ float ss[256], ss2[256];
    int l  = threadIdx.x & 63;
    int gq = threadIdx.x >> 6;
    int o  = blockIdx.x * 64 + l;
    float s = 0.f, s2 = 0.f;
    if (o < Cout) {
        for (int bn = gq; bn < B4 * NPTS; bn += 4) {
            long ix = (long)bn * Cout + o;
            s += sumh[ix]; s2 += sumsq[ix];
        }
    }
    ss[threadIdx.x] = s; ss2[threadIdx.x] = s2;
    __syncthreads();
    if (gq == 0 && o < Cout) {
        double S  = (double)ss[l]  + ss[l + 64]  + ss[l + 128]  + ss[l + 192];
        double S2 = (double)ss2[l] + ss2[l + 64] + ss2[l + 128] + ss2[l + 192];
        const double invM = 1.0 / (double)(B4 * NPTS * KNN);
        double mean = S * invM;
        double var  = S2 * invM - mean * mean;
        float sc = g[o] * rsqrtf((float)var + 1e-5f);
        st[o] = sc;
        st[Cout + o] = be[o] - (float)mean * sc;
    }
}

// ---------------------------------------------------------------------------
__global__ void stats2_kernel(const float* __restrict__ ps, const float* __restrict__ pq,
                              const float* __restrict__ g, const float* __restrict__ be,
                              int Cout, float* __restrict__ st)
{
    int o = blockIdx.x * 256 + threadIdx.x;
    if (o >= Cout) return;
    double S = 0.0, S2 = 0.0;
    for (int b = 0; b < B4; b++) {
        S  += (double)ps[(long)b * Cout + o];
        S2 += (double)pq[(long)b * Cout + o];
    }
    const double invM = 1.0 / (double)(B4 * NPTS * KNN);
    double mean = S * invM;
    double var  = S2 * invM - mean * mean;
    float sc = g[o] * rsqrtf((float)var + 1e-5f);
    st[o] = sc;
    st[Cout + o] = be[o] - (float)mean * sc;
}

// ---------------------------------------------------------------------------
// affine+lrelu on k-extremum; bf16 hi/lo transposed outputs; fp32 opt (L0)
__global__ void finalize_kernel(const float* __restrict__ maxh, const float* __restrict__ minh,
                                const float* __restrict__ st, int Cout,
                                float* __restrict__ Xvar, float* __restrict__ Xsh,
                                int voff, int writeF32,
                                __nv_bfloat16* __restrict__ XvTh, __nv_bfloat16* __restrict__ XvTl,
                                __nv_bfloat16* __restrict__ XsTh, __nv_bfloat16* __restrict__ XsTl)
{
    __shared__ float T[B4][32][33];
    int o0 = blockIdx.x * 32, n0 = blockIdx.y * 32;
    int tx = threadIdx.x, ty = threadIdx.y;
    int o = o0 + tx;
    bool ov = (o < Cout);
    float sc = ov ? st[o] : 0.f;
    float tr = ov ? st[Cout + o] : 0.f;
    const float* src = (sc >= 0.f) ? maxh : minh;
    for (int r = ty; r < 32; r += 8) {
        int n = n0 + r;
        float vb[B4];
#pragma unroll
        for (int b = 0; b < B4; b++) {
            float vv = 0.f;
            if (ov) {
                float h = src[(long)(b * NPTS + n) * Cout + o];
                float yv = fmaf(sc, h, tr);
                vv = (yv >= 0.f) ? yv : 0.2f * yv;
            }
            vb[b] = vv;
            if (writeF32) T[b][r][tx] = vv;
        }
        if (ov) {
            int col = voff + o;
#pragma unroll
            for (int b = 0; b < B4; b++) {
                long ix = ((long)(b * 256 + n)) * 4096 + col;
                __nv_bfloat16 h = __float2bfloat16(vb[b]);
                XvTh[ix] = h;
                XvTl[ix] = __float2bfloat16(vb[b] - __bfloat162float(h));
            }
            float tp = 0.5f * (vb[0] + vb[1]);
            long ix2 = (long)n * 4096 + col;
            __nv_bfloat16 h2 = __float2bfloat16(tp);
            XsTh[ix2] = h2;
            XsTl[ix2] = __float2bfloat16(tp - __bfloat162float(h2));
        }
    }
    if (writeF32) {
        __syncthreads();
        for (int r = ty; r < 32; r += 8) {
            int oc = o0 + r;
            if (oc < Cout) {
                int n = n0 + tx;
                float tp = 0.5f * (T[0][tx][r] + T[1][tx][r]);
#pragma unroll
                for (int b = 0; b < B4; b++)
                    Xvar[((long)b * 64 + voff + oc) * NPTS + n] = T[b][tx][r];
                Xsh[(long)(voff + oc) * NPTS + n] = tp;
            }
        }
    }
}

// ---------------------------------------------------------------------------
__global__ void final_bn_kernel(const float* __restrict__ ypv, const float* __restrict__ yps,
                                const float* __restrict__ g, const float* __restrict__ be,
                                float* __restrict__ out)
{
    int o = blockIdx.x, t = threadIdx.x;
    float sh = 0.f;
#pragma unroll
    for (int sp = 0; sp < 8; sp++) sh += yps[(long)sp * 65536 + o * 256 + t];
    float v[B4];
    float s = 0.f, s2 = 0.f;
#pragma unroll
    for (int b = 0; b < B4; b++) {
        float xv = sh;
#pragma unroll
        for (int sp = 0; sp < 8; sp++)
            xv += ypv[(long)(b * 8 + sp) * 65536 + o * 256 + t];
        v[b] = xv; s += xv; s2 += xv * xv;
    }
    __shared__ float rs[256], rs2[256];
    rs[t] = s; rs2[t] = s2;
    __syncthreads();
    for (int off = 128; off > 0; off >>= 1) {
        if (t < off) { rs[t] += rs[t + off]; rs2[t] += rs2[t + off]; }
        __syncthreads();
    }
    float mean = rs[0] * (1.f / 1024.f);
    float var  = rs2[0] * (1.f / 1024.f) - mean * mean;
    float sc = g[o] * rsqrtf(var + 1e-5f);
    float tr = be[o] - mean * sc;
#pragma unroll
    for (int b = 0; b < B4; b++) {
        float yv = fmaf(sc, v[b], tr);
        out[(long)b * 65536 + o * 256 + t] = (yv >= 0.f) ? yv : 0.2f * yv;
    }
}

// ---------------------------------------------------------------------------
extern "C" void kernel_launch(void* const* d_in, const int* in_sizes, int n_in,
                              void* d_out, int out_size)
{
    const float* x = (const float*)d_in[0];
    const float* w[5]  = {(const float*)d_in[1], (const float*)d_in[4], (const float*)d_in[7],
                          (const float*)d_in[10], (const float*)d_in[13]};
    const float* gm[5] = {(const float*)d_in[2], (const float*)d_in[5], (const float*)d_in[8],
                          (const float*)d_in[11], (const float*)d_in[14]};
    const float* bt[5] = {(const float*)d_in[3], (const float*)d_in[6], (const float*)d_in[9],
                          (const float*)d_in[12], (const float*)d_in[15]};
    float* out = (float*)d_out;

    float *pA, *pB2, *pAs, *pBs, *pMax, *pMin, *pSum, *pSq;
    float *pXv, *pXs, *pYpv, *pYps, *pSt, *pP0;
    __nv_bfloat16 *pAhi, *pAlo, *pBhi, *pBlo;
    int* pIdx;
    cudaGetSymbolAddress((void**)&pA, g_A);
    cudaGetSymbolAddress((void**)&pB2, g_B2);
    cudaGetSymbolAddress((void**)&pAs, g_Ash);
    cudaGetSymbolAddress((void**)&pBs, g_Bsh);
    cudaGetSymbolAddress((void**)&pMax, g_maxh);
    cudaGetSymbolAddress((void**)&pMin, g_minh);
    cudaGetSymbolAddress((void**)&pSum, g_sumh);
    cudaGetSymbolAddress((void**)&pSq, g_sumsq);
    cudaGetSymbolAddress((void**)&pXv, g_Xvar);
    cudaGetSymbolAddress((void**)&pXs, g_Xsh);
    cudaGetSymbolAddress((void**)&pYpv, g_ypv);
    cudaGetSymbolAddress((void**)&pYps, g_yps);
    cudaGetSymbolAddress((void**)&pSt, g_st);
    cudaGetSymbolAddress((void**)&pP0, g_P0);
    cudaGetSymbolAddress((void**)&pIdx, g_idx);
    cudaGetSymbolAddress((void**)&pAhi, g_Ahi);
    cudaGetSymbolAddress((void**)&pAlo, g_Alo);
    cudaGetSymbolAddress((void**)&pBhi, g_Bhi);
    cudaGetSymbolAddress((void**)&pBlo, g_Blo);

    static cudaStream_t sSide = nullptr;
    static cudaEvent_t evF1 = nullptr, evJ1 = nullptr, evF2 = nullptr, evJ2 = nullptr;
    if (!sSide) {
        cudaStreamCreateWithFlags(&sSide, cudaStreamNonBlocking);
        cudaEventCreateWithFlags(&evF1, cudaEventDisableTiming);
        cudaEventCreateWithFlags(&evJ1, cudaEventDisableTiming);
        cudaEventCreateWithFlags(&evF2, cudaEventDisableTiming);
        cudaEventCreateWithFlags(&evJ2, cudaEventDisableTiming);
    }

    cudaFuncSetAttribute(hgemm_kernel, cudaFuncAttributeMaxDynamicSharedMemorySize, HG_SMEM);
    cudaFuncSetAttribute(gather2_kernel, cudaFuncAttributeMaxDynamicSharedMemorySize, G2_SMEM);

    // ---- fork: weight splitting on side stream, overlapped with knn/L0/L1 ----
    cudaEventRecord(evF1, 0);
    cudaStreamWaitEvent(sSide, evF1, 0);
    wsplit_kernel<<<dim3(1, 384), 256, 0, sSide>>>(w[2], 768, 192,
        pAhi + AV2, pAlo + AV2, pAhi + ASH2, pAlo + ASH2);
    wsplit_kernel<<<dim3(3, 1536), 256, 0, sSide>>>(w[3], 3072, 768,
        pAhi + AV3, pAlo + AV3, pAhi + ASH3, pAlo + ASH3);
    w4split_kernel<<<4096, 256, 0, sSide>>>(w[4],
        pAhi + W4V, pAlo + W4V, pAhi + W4S, pAlo + W4S);
    cudaEventRecord(evJ1, sSide);

    xpose_kernel<<<12, 256>>>(x, pP0);
    knn_kernel<<<dim3(32, B4), 256>>>(x, pIdx);

    // ---- L0 (SIMT, K=3) ----
    gemm_kernel<<<dim3(1, 4, B4), 256>>>(pP0, 768, w[0], 6, 0, 3, 48, 96, 3,
        nullptr, nullptr, 0, 0, pA, pB2, 0, (long)NPTS * 48, 48, 1, 1, 16);
    gather_kernel<<<dim3(1, B4 * NPTS), 256>>>(pA, pB2, pIdx, 48, pMax, pMin, pSum, pSq);
    stats_kernel<<<1, 256>>>(pSum, pSq, gm[0], bt[0], 48, pSt);
    finalize_kernel<<<dim3(2, 8), dim3(32, 8)>>>(pMax, pMin, pSt, 48, pXv, pXs, 0, 1,
        pBhi + XV, pBlo + XV, pBhi + XSH, pBlo + XSH);

    // ---- L1 (SIMT, K=48) ----
    gemm_kernel<<<dim3(3, 4, 1), 256>>>(pXs, 0, w[1], 192, 48, 144, 192, 384, 48,
        nullptr, nullptr, 0, 0, pAs, pBs, 0, 0, 192, 1, 1, 48);
    gemm_kernel<<<dim3(3, 4, B4), 256>>>(pXv, (long)64 * NPTS, w[1], 192, 0, 96, 192, 384, 48,
        pAs, pBs, 1, 0, pA, pB2, 0, (long)NPTS * 192, 192, 1, 1, 48);
    gather_kernel<<<dim3(1, B4 * NPTS), 256>>>(pA, pB2, pIdx, 192, pMax, pMin, pSum, pSq);
    stats_kernel<<<3, 256>>>(pSum, pSq, gm[1], bt[1], 192, pSt);
    finalize_kernel<<<dim3(6, 8), dim3(32, 8)>>>(pMax, pMin, pSt, 192, pXv, pXs, 48, 0,
        pBhi + XV, pBlo + XV, pBhi + XSH, pBlo + XSH);

    // ---- join: weights ready before L2 HMMA ----
    cudaStreamWaitEvent(0, evJ1, 0);

    // ---- L2 (HMMA, K=192) ----
    hgemm_kernel<<<dim3(12, 2, 3), 256, HG_SMEM>>>(pAhi + ASH2, pAlo + ASH2, 192,
        pBhi + XSH + 48, pBlo + XSH + 48, 0, 768, 3, 2,
        pAs, pBs, 0, (long)NPTS * 768, nullptr, nullptr, 0, 0, 0);
    hgemm_kernel<<<dim3(12, 2, B4), 256, HG_SMEM>>>(pAhi + AV2, pAlo + AV2, 192,
        pBhi + XV + 48, pBlo + XV + 48, 1048576, 768, 1, 6,
        pA, pB2, (long)NPTS * 768, 0, pAs, pBs, 3, (long)NPTS * 768, 0);
    gather2_kernel<<<dim3(12, B4), 256, G2_SMEM>>>(pA, pB2, pIdx, 768, pMax, pMin, pSum, pSq);
    stats2_kernel<<<3, 256>>>(pSum, pSq, gm[2], bt[2], 768, pSt);
    finalize_kernel<<<dim3(24, 8), dim3(32, 8)>>>(pMax, pMin, pSt, 768, pXv, pXs, 240, 0,
        pBhi + XV, pBlo + XV, pBhi + XSH, pBlo + XSH);

    // ---- L3 (HMMA, K=768) ----
    hgemm_kernel<<<dim3(48, 2, 2), 256, HG_SMEM>>>(pAhi + ASH3, pAlo + ASH3, 768,
        pBhi + XSH + 240, pBlo + XSH + 240, 0, 3072, 2, 12,
        pAs, pBs, 0, (long)NPTS * 3072, nullptr, nullptr, 0, 0, 0);
    hgemm_kernel<<<dim3(48, 2, B4), 256, HG_SMEM>>>(pAhi + AV3, pAlo + AV3, 768,
        pBhi + XV + 240, pBlo + XV + 240, 1048576, 3072, 1, 24,
        pA, pB2, (long)NPTS * 3072, 0, pAs, pBs, 2, (long)NPTS * 3072, 0);
    gather2_kernel<<<dim3(48, B4), 256, G2_SMEM>>>(pA, pB2, pIdx, 3072, pMax, pMin, pSum, pSq);
    stats2_kernel<<<12, 256>>>(pSum, pSq, gm[3], bt[3], 3072, pSt);
    finalize_kernel<<<dim3(96, 8), dim3(32, 8)>>>(pMax, pMin, pSt, 3072, pXv, pXs, 1008, 0,
        pBhi + XV, pBlo + XV, pBhi + XSH, pBlo + XSH);

    // ---- final projections: var on main, shared concurrently on side ----
    cudaEventRecord(evF2, 0);
    cudaStreamWaitEvent(sSide, evF2, 0);
    hgemm_kernel<<<dim3(2, 2, 8), 256, HG_SMEM, sSide>>>(pAhi + W4S, pAlo + W4S, 4096,
        pBhi + XSH, pBlo + XSH, 0, 256, 8, 16,
        pYps, pYps, 0, 0, nullptr, nullptr, 0, 0, 1);
    cudaEventRecord(evJ2, sSide);
    hgemm_kernel<<<dim3(2, 2, 32), 256, HG_SMEM>>>(pAhi + W4V, pAlo + W4V, 4096,
        pBhi + XV, pBlo + XV, 1048576, 256, 8, 16,
        pYpv, pYpv, 0, 0, nullptr, nullptr, 0, 0, 1);
    cudaStreamWaitEvent(0, evJ2, 0);
    final_bn_kernel<<<256, 256>>>(pYpv, pYps, gm[4], bt[4], out);
}

// round 15
// speedup vs baseline: 1.0441x; 1.0062x over previous
#include <cuda_runtime.h>
#include <cuda_bf16.h>
#include <cstdint>

#define B4    4
#define NPTS  256
#define KNN   27
#define MAXC  3072
#define VTOT  4080
// bf16 A-pool offsets (elements)
#define AV2   0L
#define ASH2  294912L
#define AV3   589824L
#define ASH3  5308416L
#define W4V   10027008L
#define W4S   11075584L
#define ABFN  12124160L
// bf16 B-pool offsets
#define XV    0L
#define XSH   4194304L
#define BBFN  5242880L

__device__ __align__(256) float g_A    [B4 * NPTS * MAXC];
__device__ __align__(256) float g_B2   [B4 * NPTS * MAXC];
__device__ __align__(256) float g_Ash  [2 * NPTS * MAXC];
__device__ __align__(256) float g_Bsh  [2 * NPTS * MAXC];
__device__ __align__(256) float g_maxh [B4 * NPTS * MAXC];
__device__ __align__(256) float g_minh [B4 * NPTS * MAXC];
__device__ __align__(256) float g_sumh [B4 * NPTS * MAXC];
__device__ __align__(256) float g_sumsq[B4 * NPTS * MAXC];
__device__ __align__(256) float g_Xvar [B4 * 64 * NPTS];     // fp32 L0 out only
__device__ __align__(256) float g_Xsh  [64 * NPTS];
__device__ __align__(256) float g_ypv  [32 * 256 * NPTS];
__device__ __align__(256) float g_yps  [8 * 256 * NPTS];
__device__ __align__(256) float g_st   [2 * MAXC];
__device__ __align__(256) float g_P0   [B4 * 3 * NPTS];
__device__ __align__(256) int   g_idx  [B4 * NPTS * KNN];
__device__ __align__(256) __nv_bfloat16 g_Ahi[ABFN];
__device__ __align__(256) __nv_bfloat16 g_Alo[ABFN];
__device__ __align__(256) __nv_bfloat16 g_Bhi[BBFN];
__device__ __align__(256) __nv_bfloat16 g_Blo[BBFN];

// ---------------------------------------------------------------------------
__global__ void xpose_kernel(const float* __restrict__ x, float* __restrict__ P0)
{
    int id = blockIdx.x * 256 + threadIdx.x;
    if (id >= B4 * 3 * NPTS) return;
    int b = id / (3 * NPTS), r = id % (3 * NPTS);
    P0[id] = x[((long)b * NPTS + (r % NPTS)) * 3 + (r / NPTS)];
}

// ---------------------------------------------------------------------------
__global__ void knn_kernel(const float* __restrict__ x, int* __restrict__ idxout)
{
    __shared__ float px[NPTS], py[NPTS], pz[NPTS];
    int b = blockIdx.y, t = threadIdx.x;
    int w = t >> 5, lane = t & 31;
    {
        const float* xb = x + (long)b * NPTS * 3;
        px[t] = xb[t * 3 + 0]; py[t] = xb[t * 3 + 1]; pz[t] = xb[t * 3 + 2];
    }
    __syncthreads();
    int i = blockIdx.x * 8 + w;
    float xi = px[i], yi = py[i], zi = pz[i];
    float d[8];
#pragma unroll
    for (int m = 0; m < 8; m++) {
        int j = lane + 32 * m;
        float dx = xi - px[j], dy = yi - py[j], dz = zi - pz[j];
        d[m] = __fadd_rn(__fadd_rn(__fmul_rn(dx, dx), __fmul_rn(dy, dy)), __fmul_rn(dz, dz));
    }
    for (int k = 0; k < KNN; k++) {
        float bv = d[0]; int bm = 0;
#pragma unroll
        for (int m = 1; m < 8; m++) if (d[m] < bv) { bv = d[m]; bm = m; }
        int bj = lane + 32 * bm;
#pragma unroll
        for (int off = 16; off > 0; off >>= 1) {
            float ov = __shfl_down_sync(0xffffffffu, bv, off);
            int   oj = __shfl_down_sync(0xffffffffu, bj, off);
            if (ov < bv || (ov == bv && oj < bj)) { bv = ov; bj = oj; }
        }
        bj = __shfl_sync(0xffffffffu, bj, 0);
        if (lane == 0) idxout[((long)b * NPTS + i) * KNN + k] = bj;
        if ((bj & 31) == lane) {
            int m = bj >> 5;
#pragma unroll
            for (int mm = 0; mm < 8; mm++) if (mm == m) d[mm] = 3.4e38f;
        }
    }
}

// ---------------------------------------------------------------------------
// Vectorized, division-free weight split; 2 rows per thread.
__global__ void wsplit_kernel(const float* __restrict__ w, int Cout, int Cp,
                              __nv_bfloat16* __restrict__ Avh, __nv_bfloat16* __restrict__ Avl,
                              __nv_bfloat16* __restrict__ Ash, __nv_bfloat16* __restrict__ Asl)
{
    int c4 = blockIdx.x * 256 + threadIdx.x;
    if (c4 >= Cp) return;
    int Cp4 = Cp >> 2;
    int q = (c4 >= Cp4) + (c4 >= 2 * Cp4) + (c4 >= 3 * Cp4);
    int k4 = c4 - q * Cp4;
    __nv_bfloat16* ph = ((q & 1) == 0) ? Avh : Ash;
    __nv_bfloat16* pl = ((q & 1) == 0) ? Avl : Asl;
    float4 vv[2];
#pragma unroll
    for (int r = 0; r < 2; r++) {
        int m = blockIdx.y * 2 + r;
        vv[r] = reinterpret_cast<const float4*>(w)[(long)m * Cp + c4];
    }
#pragma unroll
    for (int r = 0; r < 2; r++) {
        int m = blockIdx.y * 2 + r;
        float4 v = vv[r];
        __nv_bfloat16 hx = __float2bfloat16(v.x), hy = __float2bfloat16(v.y);
        __nv_bfloat16 hz = __float2bfloat16(v.z), hw = __float2bfloat16(v.w);
        __nv_bfloat16 lx = __float2bfloat16(v.x - __bfloat162float(hx));
        __nv_bfloat16 ly = __float2bfloat16(v.y - __bfloat162float(hy));
        __nv_bfloat16 lz = __float2bfloat16(v.z - __bfloat162float(hz));
        __nv_bfloat16 lw = __float2bfloat16(v.w - __bfloat162float(hw));
        long dst = (long)((q >= 2) ? m + Cout : m) * Cp + k4 * 4;
        *reinterpret_cast<__nv_bfloat162*>(ph + dst)     = __halves2bfloat162(hx, hy);
        *reinterpret_cast<__nv_bfloat162*>(ph + dst + 2) = __halves2bfloat162(hz, hw);
        *reinterpret_cast<__nv_bfloat162*>(pl + dst)     = __halves2bfloat162(lx, ly);
        *reinterpret_cast<__nv_bfloat162*>(pl + dst + 2) = __halves2bfloat162(lz, lw);
    }
}

// ---------------------------------------------------------------------------
__global__ void w4split_kernel(const float* __restrict__ w4,
                               __nv_bfloat16* __restrict__ Avh, __nv_bfloat16* __restrict__ Avl,
                               __nv_bfloat16* __restrict__ Ash, __nv_bfloat16* __restrict__ Asl)
{
    int id = blockIdx.x * 256 + threadIdx.x;
    if (id >= 256 * 4096) return;
    int o = id >> 12, vc = id & 4095;
    float vv = 0.f, vs = 0.f;
    if (vc < VTOT) {
        int CL, off4, voff;
        if (vc < 48)        { CL = 48;   off4 = 0;    voff = 0;    }
        else if (vc < 240)  { CL = 192;  off4 = 96;   voff = 48;   }
        else if (vc < 1008) { CL = 768;  off4 = 480;  voff = 240;  }
        else                { CL = 3072; off4 = 2016; voff = 1008; }
        int c = vc - voff;
        vv = w4[(long)o * 8160 + off4 + c];
        vs = w4[(long)o * 8160 + off4 + CL + c];
    }
    __nv_bfloat16 h1 = __float2bfloat16(vv);
    Avh[id] = h1; Avl[id] = __float2bfloat16(vv - __bfloat162float(h1));
    __nv_bfloat16 h2 = __float2bfloat16(vs);
    Ash[id] = h2; Asl[id] = __float2bfloat16(vs - __bfloat162float(h2));
}

// ---------------------------------------------------------------------------
// SIMT GEMM for layers 0-1 (proven R2 version)
__global__ __launch_bounds__(256, 2)
void gemm_kernel(const float* __restrict__ P, long pstride,
                 const float* __restrict__ W, int ldw, int coffA, int coffB,
                 int Cout, int Mrows, int Kc,
                 const float* __restrict__ addA, const float* __restrict__ addB,
                 int nAdd, long addstride,
                 float* __restrict__ outA, float* __restrict__ outB,
                 long osplit, long obatch, long on, long oo,
                 int S, int kchunk)
{
    int z  = blockIdx.z;
    int b  = z / S, si = z - b * S;
    int kbeg = si * kchunk;
    int kend = min(Kc, kbeg + kchunk);
    int o0 = blockIdx.x * 128, n0 = blockIdx.y * 64;
    int t  = threadIdx.x;
    int tx = t & 15, ty = t >> 4;

    __shared__ float sP[2][16][68];
    __shared__ float sW[2][16][132];

    float acc[4][8];
#pragma unroll
    for (int i = 0; i < 4; i++)
#pragma unroll
        for (int j = 0; j < 8; j++) acc[i][j] = 0.f;

    const float* Pb = P + (long)b * pstride;
    int pc = t >> 4;
    int pn = n0 + (t & 15) * 4;
    float4 rp;
    float  rw[8];

    auto ldP = [&](int k0) {
        int c = k0 + pc;
        if (c < kend) rp = *(const float4*)(Pb + (long)c * NPTS + pn);
        else          rp = make_float4(0.f, 0.f, 0.f, 0.f);
    };
    auto ldW = [&](int k0) {
#pragma unroll
        for (int i = 0; i < 2; i++) {
            int id = t + 256 * i;
            int o  = o0 + (id >> 2);
            int c4 = (id & 3) * 4;
            bool orow = (o < Mrows);
            const float* wp = W + (orow ?
                ((long)((o < Cout) ? o : (o - Cout)) * ldw + ((o < Cout) ? coffA : coffB)) : 0);
#pragma unroll
            for (int j = 0; j < 4; j++) {
                int c = k0 + c4 + j;
                rw[i * 4 + j] = (orow && c < kend) ? wp[c] : 0.f;
            }
        }
    };
    auto stPW = [&](int buf) {
        *(float4*)&sP[buf][pc][(t & 15) * 4] = rp;
#pragma unroll
        for (int i = 0; i < 2; i++) {
            int id = t + 256 * i;
            int o  = id >> 2;
            int c4 = (id & 3) * 4;
#pragma unroll
            for (int j = 0; j < 4; j++) sW[buf][c4 + j][o] = rw[i * 4 + j];
        }
    };

    ldP(kbeg); ldW(kbeg);
    stPW(0);
    __syncthreads();
    int buf = 0;
    for (int k0 = kbeg; k0 < kend; k0 += 16) {
        bool nx = (k0 + 16) < kend;
        if (nx) { ldP(k0 + 16); ldW(k0 + 16); }
#pragma unroll
        for (int k = 0; k < 16; k++) {
            float4 a  = *(const float4*)&sP[buf][k][ty * 4];
            float4 b0 = *(const float4*)&sW[buf][k][tx * 4];
            float4 b1 = *(const float4*)&sW[buf][k][64 + tx * 4];
            float av[4] = {a.x, a.y, a.z, a.w};
            float bv[8] = {b0.x, b0.y, b0.z, b0.w, b1.x, b1.y, b1.z, b1.w};
#pragma unroll
            for (int i = 0; i < 4; i++)
#pragma unroll
                for (int j = 0; j < 8; j++)
                    acc[i][j] = fmaf(av[i], bv[j], acc[i][j]);
        }
        if (nx) stPW(buf ^ 1);
        __syncthreads();
        buf ^= 1;
    }
#pragma unroll
    for (int i = 0; i < 4; i++) {
        int n = n0 + ty * 4 + i;
#pragma unroll
        for (int j = 0; j < 8; j++) {
            int o = o0 + tx * 4 + (j & 3) + (j >> 2) * 64;
            if (o >= Mrows) continue;
            bool isA = (o < Cout);
            int  oi  = isA ? o : o - Cout;
            float v = acc[i][j];
            const float* ap = isA ? addA : addB;
            for (int s = 0; s < nAdd; s++)
                v += ap[(long)s * addstride + (long)n * Cout + oi];
            float* op = isA ? outA : outB;
            op[(long)si * osplit + (long)b * obatch + (long)n * on + (long)oi * oo] = v;
        }
    }
}

// ---------------------------------------------------------------------------
// bf16-split HMMA GEMM, cp.async double buffering (R10 proven version).
__device__ __forceinline__ void mma16816(float* c, const uint32_t* a, const uint32_t* b)
{
    asm volatile("mma.sync.aligned.m16n8k16.row.col.f32.bf16.bf16.f32 "
        "{%0,%1,%2,%3}, {%4,%5,%6,%7}, {%8,%9}, {%0,%1,%2,%3};"
        : "+f"(c[0]), "+f"(c[1]), "+f"(c[2]), "+f"(c[3])
        : "r"(a[0]), "r"(a[1]), "r"(a[2]), "r"(a[3]), "r"(b[0]), "r"(b[1]));
}
#define HG_STAGE 40960      // 4 mats x 128 rows x 80B
#define HG_SMEM  (2 * HG_STAGE)

__global__ __launch_bounds__(256, 2)
void hgemm_kernel(const __nv_bfloat16* __restrict__ Ahi, const __nv_bfloat16* __restrict__ Alo,
                  int lda,
                  const __nv_bfloat16* __restrict__ Bhi, const __nv_bfloat16* __restrict__ Blo,
                  long bstride, int Cout, int S, int ksteps,
                  float* __restrict__ outA, float* __restrict__ outB,
                  long obstride, long osplit,
                  const float* __restrict__ addA, const float* __restrict__ addB,
                  int nAdd, long addstride, int mode)
{
    extern __shared__ __align__(128) char smem[];
    const int ldb = 4096;
    int t = threadIdx.x, w = t >> 5, l = t & 31;
    int z = blockIdx.z, b = z / S, si = z - b * S;
    int o0 = blockIdx.x * 128;
    int gy = blockIdx.y;
    int kbeg = si * ksteps * 32;

    const __nv_bfloat16* aB[2] = {Ahi + (long)o0 * lda + kbeg, Alo + (long)o0 * lda + kbeg};
    const __nv_bfloat16* bB[2] = {Bhi + (long)b * bstride + (long)gy * 128 * ldb + kbeg,
                                  Blo + (long)b * bstride + (long)gy * 128 * ldb + kbeg};

    uint32_t sb0 = (uint32_t)__cvta_generic_to_shared(smem);
    int rowt = t >> 2, qt = t & 3;

    auto g2s = [&](int s, int ko) {
        uint32_t stg = sb0 + s * HG_STAGE;
#pragma unroll
        for (int h = 0; h < 2; h++)
#pragma unroll
            for (int i = 0; i < 2; i++) {
                int row = rowt + i * 64;
                uint32_t dA = stg + h * 10240 + row * 80 + qt * 16;
                const __nv_bfloat16* sA = aB[h] + (long)row * lda + ko + qt * 8;
                asm volatile("cp.async.cg.shared.global [%0], [%1], 16;" :: "r"(dA), "l"(sA));
                uint32_t dB = stg + 20480 + h * 10240 + row * 80 + qt * 16;
                const __nv_bfloat16* sB = bB[h] + (long)row * ldb + ko + qt * 8;
                asm volatile("cp.async.cg.shared.global [%0], [%1], 16;" :: "r"(dB), "l"(sB));
            }
        asm volatile("cp.async.commit_group;" ::: "memory");
    };

    float acc[2][8][4];
#pragma unroll
    for (int mt = 0; mt < 2; mt++)
#pragma unroll
        for (int j = 0; j < 8; j++)
#pragma unroll
            for (int c = 0; c < 4; c++) acc[mt][j][c] = 0.f;

    g2s(0, 0);
    if (ksteps > 1) g2s(1, 32);
    else            asm volatile("cp.async.commit_group;" ::: "memory");

    int wm = (w >> 1) * 32, wn = (w & 1) * 64;
    int lr = l >> 2, lc = (l & 3) * 4;

    for (int i = 0; i < ksteps; i++) {
        asm volatile("cp.async.wait_group 1;" ::: "memory");
        __syncthreads();
        char* stg = smem + (i & 1) * HG_STAGE;
#pragma unroll
        for (int kk = 0; kk < 2; kk++) {
            uint32_t af[2][2][4];
#pragma unroll
            for (int mt = 0; mt < 2; mt++)
#pragma unroll
                for (int h = 0; h < 2; h++) {
                    const char* base = stg + h * 10240 + (wm + mt * 16 + lr) * 80 + kk * 32 + lc;
                    af[mt][h][0] = *reinterpret_cast<const uint32_t*>(base);
                    af[mt][h][1] = *reinterpret_cast<const uint32_t*>(base + 8 * 80);
                    af[mt][h][2] = *reinterpret_cast<const uint32_t*>(base + 16);
                    af[mt][h][3] = *reinterpret_cast<const uint32_t*>(base + 8 * 80 + 16);
                }
            uint32_t bf[8][2][2];
#pragma unroll
            for (int j = 0; j < 8; j++)
#pragma unroll
                for (int h = 0; h < 2; h++) {
                    const char* base = stg + 20480 + h * 10240 + (wn + j * 8 + lr) * 80 + kk * 32 + lc;
                    bf[j][h][0] = *reinterpret_cast<const uint32_t*>(base);
                    bf[j][h][1] = *reinterpret_cast<const uint32_t*>(base + 16);
                }
#pragma unroll
            for (int mt = 0; mt < 2; mt++)
#pragma unroll
                for (int j = 0; j < 8; j++) {
                    mma16816(acc[mt][j], af[mt][0], bf[j][0]);
                    mma16816(acc[mt][j], af[mt][0], bf[j][1]);
                    mma16816(acc[mt][j], af[mt][1], bf[j][0]);
                }
        }
        __syncthreads();
        if (i + 2 < ksteps) g2s(i & 1, (i + 2) * 32);
        else                asm volatile("cp.async.commit_group;" ::: "memory");
    }

    // ---------------- epilogue: smem transpose for coalesced stores ----------
    asm volatile("cp.async.wait_group 0;" ::: "memory");
    __syncthreads();
    {
        float* so = reinterpret_cast<float*>(smem);   // [128][132] floats
#pragma unroll
        for (int mt = 0; mt < 2; mt++)
#pragma unroll
            for (int j = 0; j < 8; j++)
#pragma unroll
                for (int hf = 0; hf < 2; hf++) {
                    int ml = wm + mt * 16 + hf * 8 + lr;
                    int nl = wn + j * 8 + (l & 3) * 2;
#pragma unroll
                    for (int e = 0; e < 2; e++) {
                        float v = acc[mt][j][hf * 2 + e];
                        if (mode == 0) so[(nl + e) * 132 + ml] = v;   // [n][m]
                        else           so[ml * 132 + nl + e] = v;     // [m][n]
                    }
                }
    }
    __syncthreads();
    if (mode == 0) {
        bool isA = (o0 < Cout);
        int mo = isA ? o0 : o0 - Cout;
        float* outp = (isA ? outA : outB) + (long)si * osplit + (long)b * obstride;
        const float* ad = nAdd ? (isA ? addA : addB) : nullptr;
        const float* so = reinterpret_cast<const float*>(smem);
#pragma unroll
        for (int it = 0; it < 16; it++) {
            int idx4 = it * 256 + t;
            int n  = idx4 >> 5;
            int mq = idx4 & 31;
            float4 v = *reinterpret_cast<const float4*>(so + n * 132 + mq * 4);
            long go = (long)(gy * 128 + n) * Cout + mo + mq * 4;
            for (int s = 0; s < nAdd; s++) {
                float4 a4 = *reinterpret_cast<const float4*>(ad + (long)s * addstride + go);
                v.x += a4.x; v.y += a4.y; v.z += a4.z; v.w += a4.w;
            }
            *reinterpret_cast<float4*>(outp + go) = v;
        }
    } else {
        float* outp = outA + (long)z * 65536;
        const float* so = reinterpret_cast<const float*>(smem);
#pragma unroll
        for (int it = 0; it < 16; it++) {
            int idx4 = it * 256 + t;
            int m  = idx4 >> 5;
            int nq = idx4 & 31;
            float4 v = *reinterpret_cast<const float4*>(so + m * 132 + nq * 4);
            *reinterpret_cast<float4*>(outp + (long)(o0 + m) * 256 + gy * 128 + nq * 4) = v;
        }
    }
}

// ---------------------------------------------------------------------------
// Gather (L0/L1, small Cout)
__global__ void gather_kernel(const float* __restrict__ A, const float* __restrict__ B2,
                              const int* __restrict__ idx, int Cout,
                              float* __restrict__ maxh, float* __restrict__ minh,
                              float* __restrict__ sumh, float* __restrict__ sumsq)
{
    int bn = blockIdx.y;
    int b  = bn >> 8;
    int o  = blockIdx.x * blockDim.x + threadIdx.x;
    if (o >= Cout) return;
    const int* ip = idx + (long)bn * KNN;
    long base = (long)bn * Cout + o;
    float an = A[base];
    float Cn = B2[base] - an;
    float mx = -3.4e38f, mn = 3.4e38f, s = 0.f, s2 = 0.f;
    long bbase = (long)(b * NPTS) * Cout + o;
#pragma unroll
    for (int k = 0; k < KNN; k++) {
        float v = A[bbase + (long)ip[k] * Cout];
        mx = fmaxf(mx, v); mn = fminf(mn, v); s += v; s2 += v * v;
    }
    maxh[base]  = mx + Cn;
    minh[base]  = mn + Cn;
    sumh[base]  = s + 27.f * Cn;
    sumsq[base] = s2 + 2.f * Cn * s + 27.f * Cn * Cn;
}

// ---------------------------------------------------------------------------
// Gather with smem-cached A tile + idx (L2/L3), fusing var+shared sums.
#define G2_SMEM (65536 + 27648 + 2048)
__global__ void gather2_kernel(const float* __restrict__ A, const float* __restrict__ B2,
                               const float* __restrict__ Ashr, const float* __restrict__ B2shr,
                               const int* __restrict__ idx, int Cout,
                               float* __restrict__ maxh, float* __restrict__ minh,
                               float* __restrict__ psum, float* __restrict__ psq)
{
    extern __shared__ float sm2[];
    float* sA  = sm2;                        // [256][64] floats
    int*   sI  = (int*)(sm2 + 16384);        // [256][27] ints
    float* red = sm2 + 16384 + 6912;         // [2][256] floats
    int b = blockIdx.y, o0 = blockIdx.x * 64, t = threadIdx.x;
    int ol = t & 63, ng = t >> 6;
    const float* Ab = A + (long)b * NPTS * Cout;
    for (int i = t; i < 16384; i += 256) {
        long gix = (long)(i >> 6) * Cout + o0 + (i & 63);
        sA[i] = Ab[gix] + Ashr[gix];
    }
    for (int i = t; i < 256 * KNN; i += 256)
        sI[i] = idx[(long)b * 256 * KNN + i];
    __syncthreads();
    float accs = 0.f, accs2 = 0.f;
    for (int n0 = 0; n0 < 256; n0 += 4) {
        int n = n0 + ng;
        const int* ip = sI + n * KNN;
        float mx = -3.4e38f, mn = 3.4e38f, s = 0.f, s2 = 0.f;
#pragma unroll
        for (int k = 0; k < KNN; k++) {
            float v = sA[ip[k] * 64 + ol];
            mx = fmaxf(mx, v); mn = fminf(mn, v); s += v; s2 += v * v;
        }
        float an = sA[n * 64 + ol];
        long sbase = (long)n * Cout + o0 + ol;
        long base  = (long)b * NPTS * Cout + sbase;
        float Cn = (B2[base] + B2shr[sbase]) - an;
        maxh[base] = mx + Cn;
        minh[base] = mn + Cn;
        accs  += s + 27.f * Cn;
        accs2 += s2 + 2.f * Cn * s + 27.f * Cn * Cn;
    }
    red[t] = accs; red[256 + t] = accs2;
    __syncthreads();
    if (ng == 0) {
        float S  = red[ol] + red[ol + 64] + red[ol + 128] + red[ol + 192];
        float S2 = red[256 + ol] + red[256 + ol + 64] + red[256 + ol + 128] + red[256 + ol + 192];
        psum[(long)b * Cout + o0 + ol] = S;
        psq [(long)b * Cout + o0 + ol] = S2;
    }
}

// ---------------------------------------------------------------------------
__global__ void stats_kernel(const float* __restrict__ sumh, const float* __restrict__ sumsq,
                             const float* __restrict__ g, const float* __restrict__ be,
                             int Cout, float* __restrict__ st)
{
    __shared__ float ss[256], ss2[256];
    int l  = threadIdx.x & 63;
    int gq = threadIdx.x >> 6;
    int o  = blockIdx.x * 64 + l;
    float s = 0.f, s2 = 0.f;
    if (o < Cout) {
        for (int bn = gq; bn < B4 * NPTS; bn += 4) {
            long ix = (long)bn * Cout + o;
            s += sumh[ix]; s2 += sumsq[ix];
        }
    }
    ss[threadIdx.x] = s; ss2[threadIdx.x] = s2;
    __syncthreads();
    if (gq == 0 && o < Cout) {
        double S  = (double)ss[l]  + ss[l + 64]  + ss[l + 128]  + ss[l + 192];
        double S2 = (double)ss2[l] + ss2[l + 64] + ss2[l + 128] + ss2[l + 192];
        const double invM = 1.0 / (double)(B4 * NPTS * KNN);
        double mean = S * invM;
        double var  = S2 * invM - mean * mean;
        float sc = g[o] * rsqrtf((float)var + 1e-5f);
        st[o] = sc;
        st[Cout + o] = be[o] - (float)mean * sc;
    }
}

// ---------------------------------------------------------------------------
__global__ void stats2_kernel(const float* __restrict__ ps, const float* __restrict__ pq,
                              const float* __restrict__ g, const float* __restrict__ be,
                              int Cout, float* __restrict__ st)
{
    int o = blockIdx.x * 256 + threadIdx.x;
    if (o >= Cout) return;
    double S = 0.0, S2 = 0.0;
    for (int b = 0; b < B4; b++) {
        S  += (double)ps[(long)b * Cout + o];
        S2 += (double)pq[(long)b * Cout + o];
    }
    const double invM = 1.0 / (double)(B4 * NPTS * KNN);
    double mean = S * invM;
    double var  = S2 * invM - mean * mean;
    float sc = g[o] * rsqrtf((float)var + 1e-5f);
    st[o] = sc;
    st[Cout + o] = be[o] - (float)mean * sc;
}

// ---------------------------------------------------------------------------
// affine+lrelu on k-extremum; bf16 hi/lo transposed outputs; fp32 opt (L0)
__global__ void finalize_kernel(const float* __restrict__ maxh, const float* __restrict__ minh,
                                const float* __restrict__ st, int Cout,
                                float* __restrict__ Xvar, float* __restrict__ Xsh,
                                int voff, int writeF32,
                                __nv_bfloat16* __restrict__ XvTh, __nv_bfloat16* __restrict__ XvTl,
                                __nv_bfloat16* __restrict__ XsTh, __nv_bfloat16* __restrict__ XsTl)
{
    __shared__ float T[B4][32][33];
    int o0 = blockIdx.x * 32, n0 = blockIdx.y * 32;
    int tx = threadIdx.x, ty = threadIdx.y;
    int o = o0 + tx;
    bool ov = (o < Cout);
    float sc = ov ? st[o] : 0.f;
    float tr = ov ? st[Cout + o] : 0.f;
    const float* src = (sc >= 0.f) ? maxh : minh;
    for (int r = ty; r < 32; r += 8) {
        int n = n0 + r;
        float vb[B4];
#pragma unroll
        for (int b = 0; b < B4; b++) {
            float vv = 0.f;
            if (ov) {
                float h = src[(long)(b * NPTS + n) * Cout + o];
                float yv = fmaf(sc, h, tr);
                vv = (yv >= 0.f) ? yv : 0.2f * yv;
            }
            vb[b] = vv;
            if (writeF32) T[b][r][tx] = vv;
        }
        if (ov) {
            int col = voff + o;
#pragma unroll
            for (int b = 0; b < B4; b++) {
                long ix = ((long)(b * 256 + n)) * 4096 + col;
                __nv_bfloat16 h = __float2bfloat16(vb[b]);
                XvTh[ix] = h;
                XvTl[ix] = __float2bfloat16(vb[b] - __bfloat162float(h));
            }
            float tp = 0.5f * (vb[0] + vb[1]);
            long ix2 = (long)n * 4096 + col;
            __nv_bfloat16 h2 = __float2bfloat16(tp);
            XsTh[ix2] = h2;
            XsTl[ix2] = __float2bfloat16(tp - __bfloat162float(h2));
        }
    }
    if (writeF32) {
        __syncthreads();
        for (int r = ty; r < 32; r += 8) {
            int oc = o0 + r;
            if (oc < Cout) {
                int n = n0 + tx;
                float tp = 0.5f * (T[0][tx][r] + T[1][tx][r]);
#pragma unroll
                for (int b = 0; b < B4; b++)
                    Xvar[((long)b * 64 + voff + oc) * NPTS + n] = T[b][tx][r];
                Xsh[(long)(voff + oc) * NPTS + n] = tp;
            }
        }
    }
}

// ---------------------------------------------------------------------------
__global__ void final_bn_kernel(const float* __restrict__ ypv, const float* __restrict__ yps,
                                const float* __restrict__ g, const float* __restrict__ be,
                                float* __restrict__ out)
{
    int o = blockIdx.x, t = threadIdx.x;
    float sh = 0.f;
#pragma unroll
    for (int sp = 0; sp < 8; sp++) sh += yps[(long)sp * 65536 + o * 256 + t];
    float v[B4];
    float s = 0.f, s2 = 0.f;
#pragma unroll
    for (int b = 0; b < B4; b++) {
        float xv = sh;
#pragma unroll
        for (int sp = 0; sp < 8; sp++)
            xv += ypv[(long)(b * 8 + sp) * 65536 + o * 256 + t];
        v[b] = xv; s += xv; s2 += xv * xv;
    }
    __shared__ float rs[256], rs2[256];
    rs[t] = s; rs2[t] = s2;
    __syncthreads();
    for (int off = 128; off > 0; off >>= 1) {
        if (t < off) { rs[t] += rs[t + off]; rs2[t] += rs2[t + off]; }
        __syncthreads();
    }
    float mean = rs[0] * (1.f / 1024.f);
    float var  = rs2[0] * (1.f / 1024.f) - mean * mean;
    float sc = g[o] * rsqrtf(var + 1e-5f);
    float tr = be[o] - mean * sc;
#pragma unroll
    for (int b = 0; b < B4; b++) {
        float yv = fmaf(sc, v[b], tr);
        out[(long)b * 65536 + o * 256 + t] = (yv >= 0.f) ? yv : 0.2f * yv;
    }
}

// ---------------------------------------------------------------------------
extern "C" void kernel_launch(void* const* d_in, const int* in_sizes, int n_in,
                              void* d_out, int out_size)
{
    const float* x = (const float*)d_in[0];
    const float* w[5]  = {(const float*)d_in[1], (const float*)d_in[4], (const float*)d_in[7],
                          (const float*)d_in[10], (const float*)d_in[13]};
    const float* gm[5] = {(const float*)d_in[2], (const float*)d_in[5], (const float*)d_in[8],
                          (const float*)d_in[11], (const float*)d_in[14]};
    const float* bt[5] = {(const float*)d_in[3], (const float*)d_in[6], (const float*)d_in[9],
                          (const float*)d_in[12], (const float*)d_in[15]};
    float* out = (float*)d_out;

    float *pA, *pB2, *pAs, *pBs, *pMax, *pMin, *pSum, *pSq;
    float *pXv, *pXs, *pYpv, *pYps, *pSt, *pP0;
    __nv_bfloat16 *pAhi, *pAlo, *pBhi, *pBlo;
    int* pIdx;
    cudaGetSymbolAddress((void**)&pA, g_A);
    cudaGetSymbolAddress((void**)&pB2, g_B2);
    cudaGetSymbolAddress((void**)&pAs, g_Ash);
    cudaGetSymbolAddress((void**)&pBs, g_Bsh);
    cudaGetSymbolAddress((void**)&pMax, g_maxh);
    cudaGetSymbolAddress((void**)&pMin, g_minh);
    cudaGetSymbolAddress((void**)&pSum, g_sumh);
    cudaGetSymbolAddress((void**)&pSq, g_sumsq);
    cudaGetSymbolAddress((void**)&pXv, g_Xvar);
    cudaGetSymbolAddress((void**)&pXs, g_Xsh);
    cudaGetSymbolAddress((void**)&pYpv, g_ypv);
    cudaGetSymbolAddress((void**)&pYps, g_yps);
    cudaGetSymbolAddress((void**)&pSt, g_st);
    cudaGetSymbolAddress((void**)&pP0, g_P0);
    cudaGetSymbolAddress((void**)&pIdx, g_idx);
    cudaGetSymbolAddress((void**)&pAhi, g_Ahi);
    cudaGetSymbolAddress((void**)&pAlo, g_Alo);
    cudaGetSymbolAddress((void**)&pBhi, g_Bhi);
    cudaGetSymbolAddress((void**)&pBlo, g_Blo);

    static cudaStream_t sSide = nullptr, sSide2 = nullptr;
    static cudaEvent_t evF1, evJ1, evA, evB, evC, evD, evF2, evJ2, evK2;
    if (!sSide) {
        cudaStreamCreateWithFlags(&sSide, cudaStreamNonBlocking);
        cudaStreamCreateWithFlags(&sSide2, cudaStreamNonBlocking);
        cudaEventCreateWithFlags(&evF1, cudaEventDisableTiming);
        cudaEventCreateWithFlags(&evJ1, cudaEventDisableTiming);
        cudaEventCreateWithFlags(&evA, cudaEventDisableTiming);
        cudaEventCreateWithFlags(&evB, cudaEventDisableTiming);
        cudaEventCreateWithFlags(&evC, cudaEventDisableTiming);
        cudaEventCreateWithFlags(&evD, cudaEventDisableTiming);
        cudaEventCreateWithFlags(&evF2, cudaEventDisableTiming);
        cudaEventCreateWithFlags(&evJ2, cudaEventDisableTiming);
        cudaEventCreateWithFlags(&evK2, cudaEventDisableTiming);
    }

    cudaFuncSetAttribute(hgemm_kernel, cudaFuncAttributeMaxDynamicSharedMemorySize, HG_SMEM);
    cudaFuncSetAttribute(gather2_kernel, cudaFuncAttributeMaxDynamicSharedMemorySize, G2_SMEM);

    // ---- fork: weight splitting (sSide) + knn (sSide2), overlapped with xpose/L0/L1 ----
    cudaEventRecord(evF1, 0);
    cudaStreamWaitEvent(sSide, evF1, 0);
    wsplit_kernel<<<dim3(1, 384), 256, 0, sSide>>>(w[2], 768, 192,
        pAhi + AV2, pAlo + AV2, pAhi + ASH2, pAlo + ASH2);
    wsplit_kernel<<<dim3(3, 1536), 256, 0, sSide>>>(w[3], 3072, 768,
        pAhi + AV3, pAlo + AV3, pAhi + ASH3, pAlo + ASH3);
    w4split_kernel<<<4096, 256, 0, sSide>>>(w[4],
        pAhi + W4V, pAlo + W4V, pAhi + W4S, pAlo + W4S);
    cudaEventRecord(evJ1, sSide);

    cudaStreamWaitEvent(sSide2, evF1, 0);
    knn_kernel<<<dim3(32, B4), 256, 0, sSide2>>>(x, pIdx);
    cudaEventRecord(evK2, sSide2);

    xpose_kernel<<<12, 256>>>(x, pP0);

    // ---- L0 (SIMT, K=3) ----
    gemm_kernel<<<dim3(1, 4, B4), 256>>>(pP0, 768, w[0], 6, 0, 3, 48, 96, 3,
        nullptr, nullptr, 0, 0, pA, pB2, 0, (long)NPTS * 48, 48, 1, 1, 16);
    cudaStreamWaitEvent(0, evK2, 0);   // idx ready
    gather_kernel<<<dim3(1, B4 * NPTS), 256>>>(pA, pB2, pIdx, 48, pMax, pMin, pSum, pSq);
    stats_kernel<<<1, 256>>>(pSum, pSq, gm[0], bt[0], 48, pSt);
    finalize_kernel<<<dim3(2, 8), dim3(32, 8)>>>(pMax, pMin, pSt, 48, pXv, pXs, 0, 1,
        pBhi + XV, pBlo + XV, pBhi + XSH, pBlo + XSH);

    // ---- L1 (SIMT, K=48) ----
    gemm_kernel<<<dim3(3, 4, 1), 256>>>(pXs, 0, w[1], 192, 48, 144, 192, 384, 48,
        nullptr, nullptr, 0, 0, pAs, pBs, 0, 0, 192, 1, 1, 48);
    gemm_kernel<<<dim3(3, 4, B4), 256>>>(pXv, (long)64 * NPTS, w[1], 192, 0, 96, 192, 384, 48,
        pAs, pBs, 1, 0, pA, pB2, 0, (long)NPTS * 192, 192, 1, 1, 48);
    gather_kernel<<<dim3(1, B4 * NPTS), 256>>>(pA, pB2, pIdx, 192, pMax, pMin, pSum, pSq);
    stats_kernel<<<3, 256>>>(pSum, pSq, gm[1], bt[1], 192, pSt);
    finalize_kernel<<<dim3(6, 8), dim3(32, 8)>>>(pMax, pMin, pSt, 192, pXv, pXs, 48, 0,
        pBhi + XV, pBlo + XV, pBhi + XSH, pBlo + XSH);

    // ---- L2 (HMMA, K=192): shared on sSide CONCURRENT with var on main ----
    cudaEventRecord(evA, 0);
    cudaStreamWaitEvent(sSide, evA, 0);
    hgemm_kernel<<<dim3(12, 2, 1), 256, HG_SMEM, sSide>>>(pAhi + ASH2, pAlo + ASH2, 192,
        pBhi + XSH + 48, pBlo + XSH + 48, 0, 768, 1, 6,
        pAs, pBs, 0, 0, nullptr, nullptr, 0, 0, 0);
    cudaEventRecord(evB, sSide);
    cudaStreamWaitEvent(0, evJ1, 0);   // weights ready (main)
    hgemm_kernel<<<dim3(12, 2, B4), 256, HG_SMEM>>>(pAhi + AV2, pAlo + AV2, 192,
        pBhi + XV + 48, pBlo + XV + 48, 1048576, 768, 1, 6,
        pA, pB2, (long)NPTS * 768, 0, nullptr, nullptr, 0, 0, 0);
    cudaStreamWaitEvent(0, evB, 0);
    gather2_kernel<<<dim3(12, B4), 256, G2_SMEM>>>(pA, pB2, pAs, pBs, pIdx, 768,
        pMax, pMin, pSum, pSq);
    stats2_kernel<<<3, 256>>>(pSum, pSq, gm[2], bt[2], 768, pSt);
    finalize_kernel<<<dim3(24, 8), dim3(32, 8)>>>(pMax, pMin, pSt, 768, pXv, pXs, 240, 0,
        pBhi + XV, pBlo + XV, pBhi + XSH, pBlo + XSH);

    // ---- L3 (HMMA, K=768): shared on sSide CONCURRENT with var on main ----
    cudaEventRecord(evC, 0);
    cudaStreamWaitEvent(sSide, evC, 0);
    hgemm_kernel<<<dim3(48, 2, 1), 256, HG_SMEM, sSide>>>(pAhi + ASH3, pAlo + ASH3, 768,
        pBhi + XSH + 240, pBlo + XSH + 240, 0, 3072, 1, 24,
        pAs, pBs, 0, 0, nullptr, nullptr, 0, 0, 0);
    cudaEventRecord(evD, sSide);
    hgemm_kernel<<<dim3(48, 2, B4), 256, HG_SMEM>>>(pAhi + AV3, pAlo + AV3, 768,
        pBhi + XV + 240, pBlo + XV + 240, 1048576, 3072, 1, 24,
        pA, pB2, (long)NPTS * 3072, 0, nullptr, nullptr, 0, 0, 0);
    cudaStreamWaitEvent(0, evD, 0);
    gather2_kernel<<<dim3(48, B4), 256, G2_SMEM>>>(pA, pB2, pAs, pBs, pIdx, 3072,
        pMax, pMin, pSum, pSq);
    stats2_kernel<<<12, 256>>>(pSum, pSq, gm[3], bt[3], 3072, pSt);
    finalize_kernel<<<dim3(96, 8), dim3(32, 8)>>>(pMax, pMin, pSt, 3072, pXv, pXs, 1008, 0,
        pBhi + XV, pBlo + XV, pBhi + XSH, pBlo + XSH);

    // ---- final projections: var on main, shared concurrently on side ----
    cudaEventRecord(evF2, 0);
    cudaStreamWaitEvent(sSide, evF2, 0);
    hgemm_kernel<<<dim3(2, 2, 8), 256, HG_SMEM, sSide>>>(pAhi + W4S, pAlo + W4S, 4096,
        pBhi + XSH, pBlo + XSH, 0, 256, 8, 16,
        pYps, pYps, 0, 0, nullptr, nullptr, 0, 0, 1);
    cudaEventRecord(evJ2, sSide);
    hgemm_kernel<<<dim3(2, 2, 32), 256, HG_SMEM>>>(pAhi + W4V, pAlo + W4V, 4096,
        pBhi + XV, pBlo + XV, 1048576, 256, 8, 16,
        pYpv, pYpv, 0, 0, nullptr, nullptr, 0, 0, 1);
    cudaStreamWaitEvent(0, evJ2, 0);
    final_bn_kernel<<<256, 256>>>(pYpv, pYps, gm[4], bt[4], out);
}